// round 11
// baseline (speedup 1.0000x reference)
#include <cuda_runtime.h>
#include <cuda_bf16.h>
#include <math.h>
#include <stdint.h>

#define S_LEN  2048
#define BATCH  4
#define NHEAD  16
#define DMODEL 1024
#define DHEAD  64
#define MROWS  (BATCH * S_LEN)   // 8192
#define NZ     (BATCH * NHEAD)   // 64
#define NCHUNK 32                // scores grid.x chunks
#define LDHL   (NHEAD * 128)     // 2048 bf16 per row: per head hi(64)|lo(64)
#define LD2    (2 * DMODEL)      // 2048: hi|lo plane row stride

// ---------------- scratch (no allocations allowed) ----------------
__device__ __nv_bfloat16 g_qs[(size_t)MROWS * LDHL];   // per-head compact q hi|lo
__device__ __nv_bfloat16 g_ks[(size_t)MROWS * LDHL];   // per-head compact k hi|lo
__device__ __nv_bfloat16 g_q2[(size_t)MROWS * LD2];    // q input planes
__device__ __nv_bfloat16 g_k2[(size_t)MROWS * LD2];    // k input planes
__device__ __nv_bfloat16 g_v2[(size_t)MROWS * LD2];    // v input planes
__device__ __nv_bfloat16 g_a2[(size_t)MROWS * LD2];    // ao planes (for fc)
__device__ __nv_bfloat16 g_wq2[(size_t)DMODEL * LD2];  // weight planes
__device__ __nv_bfloat16 g_wk2[(size_t)DMODEL * LD2];
__device__ __nv_bfloat16 g_wv2[(size_t)DMODEL * LD2];
__device__ __nv_bfloat16 g_wf2[(size_t)DMODEL * LD2];
__device__ float g_vp[(size_t)MROWS * DMODEL];          // tf32-rounded V proj
__device__ float g_ao[(size_t)MROWS * DMODEL];
__device__ float g_part[(size_t)NZ * S_LEN * NCHUNK];

// ---------------- helpers ----------------
__device__ __forceinline__ void mma_tf32(float c[4], const uint32_t a[4], const uint32_t b[2]) {
    asm volatile(
        "mma.sync.aligned.m16n8k8.row.col.f32.tf32.tf32.f32 "
        "{%0,%1,%2,%3}, {%4,%5,%6,%7}, {%8,%9}, {%0,%1,%2,%3};\n"
        : "+f"(c[0]), "+f"(c[1]), "+f"(c[2]), "+f"(c[3])
        : "r"(a[0]), "r"(a[1]), "r"(a[2]), "r"(a[3]), "r"(b[0]), "r"(b[1]));
}
__device__ __forceinline__ void mma_bf16(float c[4], const uint32_t a[4], const uint32_t b[2]) {
    asm volatile(
        "mma.sync.aligned.m16n8k16.row.col.f32.bf16.bf16.f32 "
        "{%0,%1,%2,%3}, {%4,%5,%6,%7}, {%8,%9}, {%0,%1,%2,%3};\n"
        : "+f"(c[0]), "+f"(c[1]), "+f"(c[2]), "+f"(c[3])
        : "r"(a[0]), "r"(a[1]), "r"(a[2]), "r"(a[3]), "r"(b[0]), "r"(b[1]));
}
__device__ __forceinline__ uint32_t f2tf32(float x) {
    uint32_t r;
    asm("cvt.rna.tf32.f32 %0, %1;\n" : "=r"(r) : "f"(x));
    return r;
}
__device__ __forceinline__ void cp_async16(uint32_t smem_addr, const void* gptr) {
    asm volatile("cp.async.cg.shared.global [%0], [%1], 16;\n" :: "r"(smem_addr), "l"(gptr));
}
__device__ __forceinline__ void cp_commit() { asm volatile("cp.async.commit_group;\n"); }
template <int N> __device__ __forceinline__ void cp_wait() {
    asm volatile("cp.async.wait_group %0;\n" :: "n"(N));
}

// =================================================================
// Split fp32 -> bf16 hi|lo planes.
// =================================================================
__global__ __launch_bounds__(256) void split_planes(
    const float* __restrict__ x, __nv_bfloat16* __restrict__ o, int rows)
{
    const int n4 = rows * (DMODEL / 4);
    int idx = blockIdx.x * 256 + threadIdx.x;
    if (idx >= n4) return;
    const int row = idx / (DMODEL / 4);
    const int c4  = idx % (DMODEL / 4);
    const float4 v = ((const float4*)x)[idx];
    __nv_bfloat16 h[4], l[4];
    h[0] = __float2bfloat16(v.x); l[0] = __float2bfloat16(v.x - __bfloat162float(h[0]));
    h[1] = __float2bfloat16(v.y); l[1] = __float2bfloat16(v.y - __bfloat162float(h[1]));
    h[2] = __float2bfloat16(v.z); l[2] = __float2bfloat16(v.z - __bfloat162float(h[2]));
    h[3] = __float2bfloat16(v.w); l[3] = __float2bfloat16(v.w - __bfloat162float(h[3]));
    *(uint2*)(o + (size_t)row * LD2 + c4 * 4)          = *(const uint2*)h;
    *(uint2*)(o + (size_t)row * LD2 + DMODEL + c4 * 4) = *(const uint2*)l;
}

// =================================================================
// bf16x3 plane GEMM: C = A @ B^T via Ah*Bh + Ah*Bl + Al*Bh.
// BM=128, BN=64, BK=32, 2 CTAs/SM, K=1024.
// EPI 0: compact per-head bf16 hi|lo (Q/K)
// EPI 1: fp32, tf32-rounded (V proj -> PV bit-passthrough)
// EPI 2: fp32 + residual (fc)
// =================================================================
#define PS 40   // bf16 smem row stride (32 + 8 pad)

template <int EPI>
__global__ __launch_bounds__(256, 2) void proj_bf16_kernel(
    const __nv_bfloat16* __restrict__ A2,
    const __nv_bfloat16* __restrict__ B2,
    void* __restrict__ Cv,
    const float* __restrict__ Res)
{
    constexpr int BM = 128, BN = 64, BK = 32;
    constexpr int APL = BM * PS;
    constexpr int BPL = BN * PS;
    constexpr int STAGE = 2 * APL + 2 * BPL;

    extern __shared__ __nv_bfloat16 smemb[];

    const int tid  = threadIdx.x;
    const int warp = tid >> 5;
    const int lane = tid & 31;
    const int g = lane >> 2;
    const int t = lane & 3;
    const int wm0 = (warp >> 1) * 32;
    const int wn0 = (warp & 1) * 32;
    const int bm = blockIdx.y * BM, bn = blockIdx.x * BN;

    float acc[2][4][4];
#pragma unroll
    for (int i = 0; i < 2; i++)
#pragma unroll
        for (int j = 0; j < 4; j++)
#pragma unroll
            for (int r = 0; r < 4; r++) acc[i][j][r] = 0.0f;

    auto load_tile = [&](int it, int stage) {
        __nv_bfloat16* Ah = smemb + stage * STAGE;
        __nv_bfloat16* Al = Ah + APL;
        __nv_bfloat16* Bh = Al + APL;
        __nv_bfloat16* Bl = Bh + BPL;
        const int k0 = it * BK;
#pragma unroll
        for (int i = tid; i < BM * 4; i += 256) {
            const int r = i >> 2, c = (i & 3) * 8;
            const __nv_bfloat16* src = A2 + (size_t)(bm + r) * LD2 + k0 + c;
            cp_async16((uint32_t)__cvta_generic_to_shared(Ah + r * PS + c), src);
            cp_async16((uint32_t)__cvta_generic_to_shared(Al + r * PS + c), src + DMODEL);
        }
#pragma unroll
        for (int i = tid; i < BN * 4; i += 256) {
            const int r = i >> 2, c = (i & 3) * 8;
            const __nv_bfloat16* src = B2 + (size_t)(bn + r) * LD2 + k0 + c;
            cp_async16((uint32_t)__cvta_generic_to_shared(Bh + r * PS + c), src);
            cp_async16((uint32_t)__cvta_generic_to_shared(Bl + r * PS + c), src + DMODEL);
        }
    };

    load_tile(0, 0);
    cp_commit();

    constexpr int nIter = DMODEL / BK;   // 32
    for (int it = 0; it < nIter; it++) {
        if (it + 1 < nIter) {
            load_tile(it + 1, (it + 1) & 1);
            cp_commit();
            cp_wait<1>();
        } else {
            cp_wait<0>();
        }
        __syncthreads();

        const __nv_bfloat16* Ah = smemb + (it & 1) * STAGE;
        const __nv_bfloat16* Al = Ah + APL;
        const __nv_bfloat16* Bh = Al + APL;
        const __nv_bfloat16* Bl = Bh + BPL;

#pragma unroll
        for (int ks = 0; ks < 2; ks++) {
            const int k0 = ks * 16;
            uint32_t a_h[2][4], a_l[2][4], b_h[4][2], b_l[4][2];
#pragma unroll
            for (int mi = 0; mi < 2; mi++) {
                const int r0 = wm0 + mi * 16 + g;
                const int o0 = r0 * PS + k0 + 2 * t;
                const int o1 = (r0 + 8) * PS + k0 + 2 * t;
                a_h[mi][0] = *(const uint32_t*)(Ah + o0);
                a_h[mi][1] = *(const uint32_t*)(Ah + o1);
                a_h[mi][2] = *(const uint32_t*)(Ah + o0 + 8);
                a_h[mi][3] = *(const uint32_t*)(Ah + o1 + 8);
                a_l[mi][0] = *(const uint32_t*)(Al + o0);
                a_l[mi][1] = *(const uint32_t*)(Al + o1);
                a_l[mi][2] = *(const uint32_t*)(Al + o0 + 8);
                a_l[mi][3] = *(const uint32_t*)(Al + o1 + 8);
            }
#pragma unroll
            for (int ni = 0; ni < 4; ni++) {
                const int n0 = wn0 + ni * 8 + g;
                const int ob = n0 * PS + k0 + 2 * t;
                b_h[ni][0] = *(const uint32_t*)(Bh + ob);
                b_h[ni][1] = *(const uint32_t*)(Bh + ob + 8);
                b_l[ni][0] = *(const uint32_t*)(Bl + ob);
                b_l[ni][1] = *(const uint32_t*)(Bl + ob + 8);
            }
#pragma unroll
            for (int mi = 0; mi < 2; mi++)
#pragma unroll
                for (int ni = 0; ni < 4; ni++) {
                    mma_bf16(acc[mi][ni], a_l[mi], b_h[ni]);
                    mma_bf16(acc[mi][ni], a_h[mi], b_l[ni]);
                    mma_bf16(acc[mi][ni], a_h[mi], b_h[ni]);
                }
        }
        __syncthreads();
    }

    // ---- epilogue ----
#pragma unroll
    for (int mi = 0; mi < 2; mi++) {
#pragma unroll
        for (int ni = 0; ni < 4; ni++) {
            const long long row0 = bm + wm0 + mi * 16 + g;
            const long long col0 = bn + wn0 + ni * 8 + t * 2;
            if (EPI == 0) {
                __nv_bfloat16* C = (__nv_bfloat16*)Cv;
#pragma unroll
                for (int e = 0; e < 4; e++) {
                    const long long row = row0 + (e >> 1) * 8;
                    const int col = (int)col0 + (e & 1);
                    const float val = acc[mi][ni][e];
                    const __nv_bfloat16 hi = __float2bfloat16(val);
                    const __nv_bfloat16 lo = __float2bfloat16(val - __bfloat162float(hi));
                    const long long base = row * LDHL + (col >> 6) * 128 + (col & 63);
                    C[base     ] = hi;
                    C[base + 64] = lo;
                }
            } else if (EPI == 1) {
                float* C = (float*)Cv;
                float2 v0, v1;
                v0.x = __uint_as_float(f2tf32(acc[mi][ni][0]));
                v0.y = __uint_as_float(f2tf32(acc[mi][ni][1]));
                v1.x = __uint_as_float(f2tf32(acc[mi][ni][2]));
                v1.y = __uint_as_float(f2tf32(acc[mi][ni][3]));
                *(float2*)(C + row0 * DMODEL + col0) = v0;
                *(float2*)(C + (row0 + 8) * DMODEL + col0) = v1;
            } else {
                float* C = (float*)Cv;
                float2 v0 = {acc[mi][ni][0], acc[mi][ni][1]};
                float2 v1 = {acc[mi][ni][2], acc[mi][ni][3]};
                const float2 r0 = *(const float2*)(Res + row0 * DMODEL + col0);
                const float2 r1 = *(const float2*)(Res + (row0 + 8) * DMODEL + col0);
                v0.x += r0.x; v0.y += r0.y;
                v1.x += r1.x; v1.y += r1.y;
                *(float2*)(C + row0 * DMODEL + col0) = v0;
                *(float2*)(C + (row0 + 8) * DMODEL + col0) = v1;
            }
        }
    }
}

// =================================================================
// Scores: bf16x3 compensated GEMM; exp values rounded to
// tf32-representable fp32 before store (PV passes bits directly).
// =================================================================
#define SC_STRIDE 72

__global__ __launch_bounds__(256, 3) void scores_kernel(
    const __nv_bfloat16* __restrict__ qs, const __nv_bfloat16* __restrict__ ks_,
    float* __restrict__ attn, float* __restrict__ part)
{
    constexpr int BM = 128, BN = 64;
    constexpr int AT = BM * SC_STRIDE;
    constexpr int BT = BN * SC_STRIDE;

    extern __shared__ __nv_bfloat16 smemb[];
    __nv_bfloat16* Ah = smemb;
    __nv_bfloat16* Al = Ah + AT;
    __nv_bfloat16* Bh = Al + AT;
    __nv_bfloat16* Bl = Bh + BT;
    __shared__ float rowpart[2][BM];

    const int z = blockIdx.z;
    const int b = z >> 4, h = z & 15;
    const __nv_bfloat16* Aq = qs + (long long)b * S_LEN * LDHL + h * 128;
    const __nv_bfloat16* Bk = ks_ + (long long)b * S_LEN * LDHL + h * 128;
    float* C = attn + (long long)z * S_LEN * S_LEN;

    const int tid  = threadIdx.x;
    const int warp = tid >> 5;
    const int lane = tid & 31;
    const int g = lane >> 2;
    const int t = lane & 3;
    const int wm0 = (warp >> 1) * 32;
    const int wn0 = (warp & 1) * 32;
    const int wc  = warp & 1;
    const int bm = blockIdx.y * BM, bn = blockIdx.x * BN;

#pragma unroll
    for (int i = tid; i < BM * 8; i += 256) {
        const int r = i >> 3, c = (i & 7) * 8;
        const __nv_bfloat16* src = Aq + (long long)(bm + r) * LDHL + c;
        cp_async16((uint32_t)__cvta_generic_to_shared(Ah + r * SC_STRIDE + c), src);
        cp_async16((uint32_t)__cvta_generic_to_shared(Al + r * SC_STRIDE + c), src + 64);
    }
#pragma unroll
    for (int i = tid; i < BN * 8; i += 256) {
        const int r = i >> 3, c = (i & 7) * 8;
        const __nv_bfloat16* src = Bk + (long long)(bn + r) * LDHL + c;
        cp_async16((uint32_t)__cvta_generic_to_shared(Bh + r * SC_STRIDE + c), src);
        cp_async16((uint32_t)__cvta_generic_to_shared(Bl + r * SC_STRIDE + c), src + 64);
    }
    cp_commit();
    cp_wait<0>();
    __syncthreads();

    float acc[2][4][4];
#pragma unroll
    for (int i = 0; i < 2; i++)
#pragma unroll
        for (int j = 0; j < 4; j++)
#pragma unroll
            for (int r = 0; r < 4; r++) acc[i][j][r] = 0.0f;

#pragma unroll
    for (int ks = 0; ks < 4; ks++) {
        const int k0 = ks * 16;
        uint32_t a_h[2][4], a_l[2][4], b_h[4][2], b_l[4][2];
#pragma unroll
        for (int mi = 0; mi < 2; mi++) {
            const int r0 = wm0 + mi * 16 + g;
            const int o0 = r0 * SC_STRIDE + k0 + 2 * t;
            const int o1 = (r0 + 8) * SC_STRIDE + k0 + 2 * t;
            a_h[mi][0] = *(const uint32_t*)(Ah + o0);
            a_h[mi][1] = *(const uint32_t*)(Ah + o1);
            a_h[mi][2] = *(const uint32_t*)(Ah + o0 + 8);
            a_h[mi][3] = *(const uint32_t*)(Ah + o1 + 8);
            a_l[mi][0] = *(const uint32_t*)(Al + o0);
            a_l[mi][1] = *(const uint32_t*)(Al + o1);
            a_l[mi][2] = *(const uint32_t*)(Al + o0 + 8);
            a_l[mi][3] = *(const uint32_t*)(Al + o1 + 8);
        }
#pragma unroll
        for (int ni = 0; ni < 4; ni++) {
            const int n0 = wn0 + ni * 8 + g;
            const int ob = n0 * SC_STRIDE + k0 + 2 * t;
            b_h[ni][0] = *(const uint32_t*)(Bh + ob);
            b_h[ni][1] = *(const uint32_t*)(Bh + ob + 8);
            b_l[ni][0] = *(const uint32_t*)(Bl + ob);
            b_l[ni][1] = *(const uint32_t*)(Bl + ob + 8);
        }
#pragma unroll
        for (int mi = 0; mi < 2; mi++)
#pragma unroll
            for (int ni = 0; ni < 4; ni++) {
                mma_bf16(acc[mi][ni], a_l[mi], b_h[ni]);
                mma_bf16(acc[mi][ni], a_h[mi], b_l[ni]);
                mma_bf16(acc[mi][ni], a_h[mi], b_h[ni]);
            }
    }

    float rsum[2][2] = {{0.f, 0.f}, {0.f, 0.f}};
#pragma unroll
    for (int mi = 0; mi < 2; mi++) {
#pragma unroll
        for (int ni = 0; ni < 4; ni++) {
#pragma unroll
            for (int r = 0; r < 4; r++) {
                float e = __expf(0.125f * acc[mi][ni][r]);
                acc[mi][ni][r] = __uint_as_float(f2tf32(e));   // tf32-representable
            }
            rsum[mi][0] += acc[mi][ni][0] + acc[mi][ni][1];
            rsum[mi][1] += acc[mi][ni][2] + acc[mi][ni][3];

            const long long row0 = bm + wm0 + mi * 16 + g;
            const long long col0 = bn + wn0 + ni * 8 + t * 2;
            float2 v0 = {acc[mi][ni][0], acc[mi][ni][1]};
            float2 v1 = {acc[mi][ni][2], acc[mi][ni][3]};
            *(float2*)(C + row0 * S_LEN + col0) = v0;
            *(float2*)(C + (row0 + 8) * S_LEN + col0) = v1;
        }
    }
#pragma unroll
    for (int mi = 0; mi < 2; mi++)
#pragma unroll
        for (int s = 0; s < 2; s++) {
            float v = rsum[mi][s];
            v += __shfl_xor_sync(0xffffffffu, v, 1);
            v += __shfl_xor_sync(0xffffffffu, v, 2);
            if (t == 0) rowpart[wc][wm0 + mi * 16 + s * 8 + g] = v;
        }
    __syncthreads();
    if (tid < BM) {
        float p = rowpart[0][tid] + rowpart[1][tid];
        part[((long long)z * S_LEN + bm + tid) * NCHUNK + blockIdx.x] = p;
    }
}

// =================================================================
// PV kernel: inputs pre-rounded to tf32 -> zero-ALU mainloop
// (bits pass straight to MMA). Normalizes attn in place.
// =================================================================
__global__ __launch_bounds__(256, 2) void pv_kernel(
    float* __restrict__ attn, const float* __restrict__ vp,
    float* __restrict__ ao, const float* __restrict__ part)
{
    constexpr int BM = 128, BN = 64, BK = 32;
    constexpr int A_WORDS = BM * (BK + 4);
    constexpr int B_WORDS = BK * (BN + 4);
    constexpr int STAGE_WORDS = A_WORDS + B_WORDS;

    extern __shared__ float smemf[];
    __shared__ float sInv[BM];

    const int z = blockIdx.z;
    const int b = z >> 4, h = z & 15;
    float* A = attn + (long long)z * S_LEN * S_LEN;
    const float* B = vp + (long long)b * S_LEN * DMODEL + h * DHEAD;
    float* C = ao + (long long)b * S_LEN * DMODEL + h * DHEAD;

    const int tid  = threadIdx.x;
    const int warp = tid >> 5;
    const int lane = tid & 31;
    const int g = lane >> 2;
    const int t = lane & 3;
    const int wm0 = (warp >> 1) * 32;
    const int wn0 = (warp & 1) * 32;
    const int bm = blockIdx.y * BM;

    if (tid < BM) {
        const float* p = part + ((long long)z * S_LEN + bm + tid) * NCHUNK;
        float s = 0.0f;
#pragma unroll
        for (int j = 0; j < NCHUNK; j++) s += p[j];
        sInv[tid] = 1.0f / s;
    }

    float acc[2][4][4];
#pragma unroll
    for (int i = 0; i < 2; i++)
#pragma unroll
        for (int j = 0; j < 4; j++)
#pragma unroll
            for (int r = 0; r < 4; r++) acc[i][j][r] = 0.0f;

    auto load_tile = [&](int it, int stage) {
        float* As = smemf + stage * STAGE_WORDS;
        float* Bs = As + A_WORDS;
        const int k0 = it * BK;
#pragma unroll
        for (int i = tid; i < BM * BK / 4; i += 256) {
            int r = i / 8, c = (i % 8) * 4;
            uint32_t dst = (uint32_t)__cvta_generic_to_shared(As + r * (BK + 4) + c);
            cp_async16(dst, A + (long long)(bm + r) * S_LEN + k0 + c);
        }
#pragma unroll
        for (int i = tid; i < BK * BN / 4; i += 256) {
            int r = i / 16, c = (i % 16) * 4;
            uint32_t dst = (uint32_t)__cvta_generic_to_shared(Bs + r * (BN + 4) + c);
            cp_async16(dst, B + (long long)(k0 + r) * DMODEL + c);
        }
    };

    load_tile(0, 0);
    cp_commit();

    const int nIter = S_LEN / BK;   // 64
    for (int it = 0; it < nIter; it++) {
        if (it + 1 < nIter) {
            load_tile(it + 1, (it + 1) & 1);
            cp_commit();
            cp_wait<1>();
        } else {
            cp_wait<0>();
        }
        __syncthreads();

        const float* As = smemf + (it & 1) * STAGE_WORDS;
        const float* Bs = As + A_WORDS;

        // write normalized attn for this tile (data already in smem)
#pragma unroll
        for (int i = tid; i < BM * BK; i += 256) {
            const int r = i >> 5, c = i & 31;
            A[(long long)(bm + r) * S_LEN + it * BK + c] = As[r * (BK + 4) + c] * sInv[r];
        }

#pragma unroll
        for (int ks = 0; ks < BK / 8; ks++) {
            uint32_t ah[2][4], bh[4][2];
#pragma unroll
            for (int mi = 0; mi < 2; mi++) {
                const int r0 = wm0 + mi * 16 + g;
                const int c0 = ks * 8 + t;
                // values already tf32-representable: pass bits directly
                ah[mi][0] = __float_as_uint(As[(r0    ) * (BK + 4) + c0    ]);
                ah[mi][1] = __float_as_uint(As[(r0 + 8) * (BK + 4) + c0    ]);
                ah[mi][2] = __float_as_uint(As[(r0    ) * (BK + 4) + c0 + 4]);
                ah[mi][3] = __float_as_uint(As[(r0 + 8) * (BK + 4) + c0 + 4]);
            }
#pragma unroll
            for (int ni = 0; ni < 4; ni++) {
                const int n0 = wn0 + ni * 8 + g;
                bh[ni][0] = __float_as_uint(Bs[(ks * 8 + t    ) * (BN + 4) + n0]);
                bh[ni][1] = __float_as_uint(Bs[(ks * 8 + t + 4) * (BN + 4) + n0]);
            }
#pragma unroll
            for (int mi = 0; mi < 2; mi++)
#pragma unroll
                for (int ni = 0; ni < 4; ni++)
                    mma_tf32(acc[mi][ni], ah[mi], bh[ni]);
        }
        __syncthreads();
    }

#pragma unroll
    for (int mi = 0; mi < 2; mi++) {
#pragma unroll
        for (int ni = 0; ni < 4; ni++) {
            const int rl0 = wm0 + mi * 16 + g;
            const long long row0 = bm + rl0;
            const long long col0 = wn0 + ni * 8 + t * 2;
            float2 v0, v1;
            v0.x = acc[mi][ni][0] * sInv[rl0];
            v0.y = acc[mi][ni][1] * sInv[rl0];
            v1.x = acc[mi][ni][2] * sInv[rl0 + 8];
            v1.y = acc[mi][ni][3] * sInv[rl0 + 8];
            *(float2*)(C + row0 * DMODEL + col0) = v0;
            *(float2*)(C + (row0 + 8) * DMODEL + col0) = v1;
        }
    }
}

// =================================================================
// In-place LayerNorm over rows of length DMODEL (1024). 256 threads.
// =================================================================
__global__ __launch_bounds__(256) void ln_kernel(float* __restrict__ x,
                                                 const float* __restrict__ gamma,
                                                 const float* __restrict__ beta)
{
    float* row = x + (size_t)blockIdx.x * DMODEL;
    const int tid = threadIdx.x;
    __shared__ float ssum[8], ssq[8];

    float v[4];
    float s = 0.0f, sq = 0.0f;
#pragma unroll
    for (int j = 0; j < 4; j++) {
        v[j] = row[tid + j * 256];
        s += v[j];
        sq += v[j] * v[j];
    }
#pragma unroll
    for (int o = 16; o > 0; o >>= 1) {
        s  += __shfl_xor_sync(0xffffffffu, s, o);
        sq += __shfl_xor_sync(0xffffffffu, sq, o);
    }
    if ((tid & 31) == 0) { ssum[tid >> 5] = s; ssq[tid >> 5] = sq; }
    __syncthreads();
    s = 0.0f; sq = 0.0f;
#pragma unroll
    for (int j = 0; j < 8; j++) { s += ssum[j]; sq += ssq[j]; }

    const float mu = s * (1.0f / DMODEL);
    const float var = sq * (1.0f / DMODEL) - mu * mu;
    const float rstd = rsqrtf(var + 1e-6f);
#pragma unroll
    for (int j = 0; j < 4; j++) {
        const int c = tid + j * 256;
        row[c] = (v[j] - mu) * rstd * gamma[c] + beta[c];
    }
}

// =================================================================
static constexpr int PROJ_SMEM = 2 * (2 * 128 * 40 + 2 * 64 * 40) * 2; // 61440 B
static constexpr int SC_SMEM   = (2 * 128 * 72 + 2 * 64 * 72) * 2;     // 55296 B
static constexpr int PV_SMEM   = 2 * (128 * 36 + 32 * 68) * 4;         // 54272 B

extern "C" void kernel_launch(void* const* d_in, const int* in_sizes, int n_in,
                              void* d_out, int out_size)
{
    const float* q     = (const float*)d_in[0];
    const float* k     = (const float*)d_in[1];
    const float* v     = (const float*)d_in[2];
    const float* w_q   = (const float*)d_in[3];
    const float* w_k   = (const float*)d_in[4];
    const float* w_v   = (const float*)d_in[5];
    const float* w_fc  = (const float*)d_in[6];
    const float* gamma = (const float*)d_in[7];
    const float* beta  = (const float*)d_in[8];

    __nv_bfloat16 *qs, *ks_, *q2, *k2, *v2, *a2, *wq2, *wk2, *wv2, *wf2;
    float *vp, *ao, *part;
    cudaGetSymbolAddress((void**)&qs, g_qs);
    cudaGetSymbolAddress((void**)&ks_, g_ks);
    cudaGetSymbolAddress((void**)&q2, g_q2);
    cudaGetSymbolAddress((void**)&k2, g_k2);
    cudaGetSymbolAddress((void**)&v2, g_v2);
    cudaGetSymbolAddress((void**)&a2, g_a2);
    cudaGetSymbolAddress((void**)&wq2, g_wq2);
    cudaGetSymbolAddress((void**)&wk2, g_wk2);
    cudaGetSymbolAddress((void**)&wv2, g_wv2);
    cudaGetSymbolAddress((void**)&wf2, g_wf2);
    cudaGetSymbolAddress((void**)&vp, g_vp);
    cudaGetSymbolAddress((void**)&ao, g_ao);
    cudaGetSymbolAddress((void**)&part, g_part);

    float* out  = (float*)d_out;
    float* attn = out + (size_t)MROWS * DMODEL;   // [B, H, Sq, Sk] fp32

    cudaFuncSetAttribute(proj_bf16_kernel<0>,
                         cudaFuncAttributeMaxDynamicSharedMemorySize, PROJ_SMEM);
    cudaFuncSetAttribute(proj_bf16_kernel<1>,
                         cudaFuncAttributeMaxDynamicSharedMemorySize, PROJ_SMEM);
    cudaFuncSetAttribute(proj_bf16_kernel<2>,
                         cudaFuncAttributeMaxDynamicSharedMemorySize, PROJ_SMEM);
    cudaFuncSetAttribute(scores_kernel,
                         cudaFuncAttributeMaxDynamicSharedMemorySize, SC_SMEM);
    cudaFuncSetAttribute(pv_kernel,
                         cudaFuncAttributeMaxDynamicSharedMemorySize, PV_SMEM);

    dim3 blk(256);
    const int actBlocks = MROWS * (DMODEL / 4) / 256;   // 8192
    const int wBlocks   = DMODEL * (DMODEL / 4) / 256;  // 1024

    // --- split inputs into bf16 hi|lo planes ---
    split_planes<<<actBlocks, blk>>>(q, q2, MROWS);
    split_planes<<<actBlocks, blk>>>(k, k2, MROWS);
    split_planes<<<actBlocks, blk>>>(v, v2, MROWS);
    split_planes<<<wBlocks, blk>>>(w_q, wq2, DMODEL);
    split_planes<<<wBlocks, blk>>>(w_k, wk2, DMODEL);
    split_planes<<<wBlocks, blk>>>(w_v, wv2, DMODEL);
    split_planes<<<wBlocks, blk>>>(w_fc, wf2, DMODEL);

    // --- projections: zero-ALU bf16x3 GEMMs ---
    {
        dim3 g(DMODEL / 64, MROWS / 128, 1);
        proj_bf16_kernel<0><<<g, blk, PROJ_SMEM>>>(q2, wq2, qs, nullptr);
        proj_bf16_kernel<0><<<g, blk, PROJ_SMEM>>>(k2, wk2, ks_, nullptr);
        proj_bf16_kernel<1><<<g, blk, PROJ_SMEM>>>(v2, wv2, vp, nullptr);  // tf32-rounded
    }

    // --- scores (bf16x3) + exp (tf32-rounded) + partials ---
    {
        dim3 g(S_LEN / 64, S_LEN / 128, NZ);
        scores_kernel<<<g, blk, SC_SMEM>>>(qs, ks_, attn, part);
    }

    // --- PV (zero-ALU tf32) + in-place softmax normalization ---
    {
        dim3 g(1, S_LEN / 128, NZ);
        pv_kernel<<<g, blk, PV_SMEM>>>(attn, vp, ao, part);
    }

    // --- fc + residual (bf16x3 from planes) ---
    split_planes<<<actBlocks, blk>>>(ao, a2, MROWS);
    {
        dim3 g(DMODEL / 64, MROWS / 128, 1);
        proj_bf16_kernel<2><<<g, blk, PROJ_SMEM>>>(a2, wf2, out, q);
    }

    // --- layernorm in place ---
    ln_kernel<<<MROWS, blk>>>(out, gamma, beta);
}

// round 12
// speedup vs baseline: 1.0696x; 1.0696x over previous
#include <cuda_runtime.h>
#include <cuda_bf16.h>
#include <math.h>
#include <stdint.h>

#define S_LEN  2048
#define BATCH  4
#define NHEAD  16
#define DMODEL 1024
#define DHEAD  64
#define MROWS  (BATCH * S_LEN)   // 8192
#define NZ     (BATCH * NHEAD)   // 64
#define NCHUNK 32                // scores grid.x chunks
#define LDHL   (NHEAD * 128)     // 2048 bf16 per row: per head hi(64)|lo(64)
#define LD2    (2 * DMODEL)      // 2048: hi|lo plane row stride

// ---------------- scratch (no allocations allowed) ----------------
__device__ __nv_bfloat16 g_qs[(size_t)MROWS * LDHL];  // per-head compact q hi|lo
__device__ __nv_bfloat16 g_ks[(size_t)MROWS * LDHL];  // per-head compact k hi|lo
__device__ __nv_bfloat16 g_q2[(size_t)MROWS * LD2];   // q input planes [row][hi|lo]
__device__ __nv_bfloat16 g_k2[(size_t)MROWS * LD2];   // k input planes
__device__ __nv_bfloat16 g_wq2[(size_t)DMODEL * LD2]; // w_q planes [out][hi|lo]
__device__ __nv_bfloat16 g_wk2[(size_t)DMODEL * LD2]; // w_k planes
__device__ float g_vp[(size_t)MROWS * DMODEL];        // tf32-rounded V proj
__device__ float g_ao[(size_t)MROWS * DMODEL];
__device__ float g_part[(size_t)NZ * S_LEN * NCHUNK];

// ---------------- helpers ----------------
__device__ __forceinline__ void mma_tf32(float c[4], const uint32_t a[4], const uint32_t b[2]) {
    asm volatile(
        "mma.sync.aligned.m16n8k8.row.col.f32.tf32.tf32.f32 "
        "{%0,%1,%2,%3}, {%4,%5,%6,%7}, {%8,%9}, {%0,%1,%2,%3};\n"
        : "+f"(c[0]), "+f"(c[1]), "+f"(c[2]), "+f"(c[3])
        : "r"(a[0]), "r"(a[1]), "r"(a[2]), "r"(a[3]), "r"(b[0]), "r"(b[1]));
}
__device__ __forceinline__ void mma_bf16(float c[4], const uint32_t a[4], const uint32_t b[2]) {
    asm volatile(
        "mma.sync.aligned.m16n8k16.row.col.f32.bf16.bf16.f32 "
        "{%0,%1,%2,%3}, {%4,%5,%6,%7}, {%8,%9}, {%0,%1,%2,%3};\n"
        : "+f"(c[0]), "+f"(c[1]), "+f"(c[2]), "+f"(c[3])
        : "r"(a[0]), "r"(a[1]), "r"(a[2]), "r"(a[3]), "r"(b[0]), "r"(b[1]));
}
__device__ __forceinline__ uint32_t f2tf32(float x) {
    uint32_t r;
    asm("cvt.rna.tf32.f32 %0, %1;\n" : "=r"(r) : "f"(x));
    return r;
}
__device__ __forceinline__ void cp_async16(uint32_t smem_addr, const void* gptr) {
    asm volatile("cp.async.cg.shared.global [%0], [%1], 16;\n" :: "r"(smem_addr), "l"(gptr));
}
__device__ __forceinline__ void cp_commit() { asm volatile("cp.async.commit_group;\n"); }
template <int N> __device__ __forceinline__ void cp_wait() {
    asm volatile("cp.async.wait_group %0;\n" :: "n"(N));
}

// =================================================================
// Split fp32 -> bf16 hi|lo planes.
// =================================================================
__global__ __launch_bounds__(256) void split_planes(
    const float* __restrict__ x, __nv_bfloat16* __restrict__ o, int rows)
{
    const int n4 = rows * (DMODEL / 4);
    int idx = blockIdx.x * 256 + threadIdx.x;
    if (idx >= n4) return;
    const int row = idx / (DMODEL / 4);
    const int c4  = idx % (DMODEL / 4);
    const float4 v = ((const float4*)x)[idx];
    __nv_bfloat16 h[4], l[4];
    h[0] = __float2bfloat16(v.x); l[0] = __float2bfloat16(v.x - __bfloat162float(h[0]));
    h[1] = __float2bfloat16(v.y); l[1] = __float2bfloat16(v.y - __bfloat162float(h[1]));
    h[2] = __float2bfloat16(v.z); l[2] = __float2bfloat16(v.z - __bfloat162float(h[2]));
    h[3] = __float2bfloat16(v.w); l[3] = __float2bfloat16(v.w - __bfloat162float(h[3]));
    *(uint2*)(o + (size_t)row * LD2 + c4 * 4)          = *(const uint2*)h;
    *(uint2*)(o + (size_t)row * LD2 + DMODEL + c4 * 4) = *(const uint2*)l;
}

// =================================================================
// Q/K projection: zero-ALU bf16x3 GEMM over precomputed planes.
// Epilogue writes compact per-head bf16 hi|lo layout.
// =================================================================
#define PS 40   // bf16 smem row stride (32 + 8 pad)

__global__ __launch_bounds__(256, 2) void proj_bf16_kernel(
    const __nv_bfloat16* __restrict__ A2,
    const __nv_bfloat16* __restrict__ B2,
    __nv_bfloat16* __restrict__ C)
{
    constexpr int BM = 128, BN = 64, BK = 32;
    constexpr int APL = BM * PS;
    constexpr int BPL = BN * PS;
    constexpr int STAGE = 2 * APL + 2 * BPL;

    extern __shared__ __nv_bfloat16 smemb[];

    const int tid  = threadIdx.x;
    const int warp = tid >> 5;
    const int lane = tid & 31;
    const int g = lane >> 2;
    const int t = lane & 3;
    const int wm0 = (warp >> 1) * 32;
    const int wn0 = (warp & 1) * 32;
    const int bm = blockIdx.y * BM, bn = blockIdx.x * BN;

    float acc[2][4][4];
#pragma unroll
    for (int i = 0; i < 2; i++)
#pragma unroll
        for (int j = 0; j < 4; j++)
#pragma unroll
            for (int r = 0; r < 4; r++) acc[i][j][r] = 0.0f;

    auto load_tile = [&](int it, int stage) {
        __nv_bfloat16* Ah = smemb + stage * STAGE;
        __nv_bfloat16* Al = Ah + APL;
        __nv_bfloat16* Bh = Al + APL;
        __nv_bfloat16* Bl = Bh + BPL;
        const int k0 = it * BK;
#pragma unroll
        for (int i = tid; i < BM * 4; i += 256) {
            const int r = i >> 2, c = (i & 3) * 8;
            const __nv_bfloat16* src = A2 + (size_t)(bm + r) * LD2 + k0 + c;
            cp_async16((uint32_t)__cvta_generic_to_shared(Ah + r * PS + c), src);
            cp_async16((uint32_t)__cvta_generic_to_shared(Al + r * PS + c), src + DMODEL);
        }
#pragma unroll
        for (int i = tid; i < BN * 4; i += 256) {
            const int r = i >> 2, c = (i & 3) * 8;
            const __nv_bfloat16* src = B2 + (size_t)(bn + r) * LD2 + k0 + c;
            cp_async16((uint32_t)__cvta_generic_to_shared(Bh + r * PS + c), src);
            cp_async16((uint32_t)__cvta_generic_to_shared(Bl + r * PS + c), src + DMODEL);
        }
    };

    load_tile(0, 0);
    cp_commit();

    constexpr int nIter = DMODEL / BK;   // 32
    for (int it = 0; it < nIter; it++) {
        if (it + 1 < nIter) {
            load_tile(it + 1, (it + 1) & 1);
            cp_commit();
            cp_wait<1>();
        } else {
            cp_wait<0>();
        }
        __syncthreads();

        const __nv_bfloat16* Ah = smemb + (it & 1) * STAGE;
        const __nv_bfloat16* Al = Ah + APL;
        const __nv_bfloat16* Bh = Al + APL;
        const __nv_bfloat16* Bl = Bh + BPL;

#pragma unroll
        for (int ks = 0; ks < 2; ks++) {
            const int k0 = ks * 16;
            uint32_t a_h[2][4], a_l[2][4], b_h[4][2], b_l[4][2];
#pragma unroll
            for (int mi = 0; mi < 2; mi++) {
                const int r0 = wm0 + mi * 16 + g;
                const int o0 = r0 * PS + k0 + 2 * t;
                const int o1 = (r0 + 8) * PS + k0 + 2 * t;
                a_h[mi][0] = *(const uint32_t*)(Ah + o0);
                a_h[mi][1] = *(const uint32_t*)(Ah + o1);
                a_h[mi][2] = *(const uint32_t*)(Ah + o0 + 8);
                a_h[mi][3] = *(const uint32_t*)(Ah + o1 + 8);
                a_l[mi][0] = *(const uint32_t*)(Al + o0);
                a_l[mi][1] = *(const uint32_t*)(Al + o1);
                a_l[mi][2] = *(const uint32_t*)(Al + o0 + 8);
                a_l[mi][3] = *(const uint32_t*)(Al + o1 + 8);
            }
#pragma unroll
            for (int ni = 0; ni < 4; ni++) {
                const int n0 = wn0 + ni * 8 + g;
                const int ob = n0 * PS + k0 + 2 * t;
                b_h[ni][0] = *(const uint32_t*)(Bh + ob);
                b_h[ni][1] = *(const uint32_t*)(Bh + ob + 8);
                b_l[ni][0] = *(const uint32_t*)(Bl + ob);
                b_l[ni][1] = *(const uint32_t*)(Bl + ob + 8);
            }
#pragma unroll
            for (int mi = 0; mi < 2; mi++)
#pragma unroll
                for (int ni = 0; ni < 4; ni++) {
                    mma_bf16(acc[mi][ni], a_l[mi], b_h[ni]);
                    mma_bf16(acc[mi][ni], a_h[mi], b_l[ni]);
                    mma_bf16(acc[mi][ni], a_h[mi], b_h[ni]);
                }
        }
        __syncthreads();
    }

    // ---- epilogue: compact per-head bf16 hi|lo ----
#pragma unroll
    for (int mi = 0; mi < 2; mi++) {
#pragma unroll
        for (int ni = 0; ni < 4; ni++) {
            const long long row0 = bm + wm0 + mi * 16 + g;
            const long long col0 = bn + wn0 + ni * 8 + t * 2;
#pragma unroll
            for (int e = 0; e < 4; e++) {
                const long long row = row0 + (e >> 1) * 8;
                const int col = (int)col0 + (e & 1);
                const float val = acc[mi][ni][e];
                const __nv_bfloat16 hi = __float2bfloat16(val);
                const __nv_bfloat16 lo = __float2bfloat16(val - __bfloat162float(hi));
                const long long base = row * LDHL + (col >> 6) * 128 + (col & 63);
                C[base     ] = hi;
                C[base + 64] = lo;
            }
        }
    }
}

// =================================================================
// Generic tensor-core tf32 GEMM (V proj, fc). BM=128, BN=64, BK=32.
// RND: epilogue rounds output to tf32-representable fp32.
// =================================================================
template <bool TRANSB, bool RES, bool RND>
__global__ __launch_bounds__(256, 2) void gemm_tc(
    const float* __restrict__ A, int lda,
    const float* __restrict__ B, int ldb,
    float* __restrict__ C, int ldc,
    int K, float alpha, const float* __restrict__ Res)
{
    constexpr int BM = 128, BN = 64, BK = 32;
    constexpr int MI = 2, NI = 4;
    constexpr int A_WORDS = BM * (BK + 4);
    constexpr int B_WORDS = TRANSB ? BN * (BK + 4) : BK * (BN + 4);
    constexpr int STAGE_WORDS = A_WORDS + B_WORDS;

    extern __shared__ float smemf[];

    const int tid  = threadIdx.x;
    const int warp = tid >> 5;
    const int lane = tid & 31;
    const int g = lane >> 2;
    const int t = lane & 3;
    const int wm0 = (warp >> 1) * 32;
    const int wn0 = (warp & 1) * 32;
    const int bm = blockIdx.y * BM, bn = blockIdx.x * BN;

    float acc[MI][NI][4];
#pragma unroll
    for (int i = 0; i < MI; i++)
#pragma unroll
        for (int j = 0; j < NI; j++)
#pragma unroll
            for (int r = 0; r < 4; r++) acc[i][j][r] = 0.0f;

    const int nIter = K / BK;

    auto load_tile = [&](int it, int stage) {
        float* As = smemf + stage * STAGE_WORDS;
        float* Bs = As + A_WORDS;
        const int k0 = it * BK;
#pragma unroll
        for (int i = tid; i < BM * BK / 4; i += 256) {
            int r = i / 8, c = (i % 8) * 4;
            uint32_t dst = (uint32_t)__cvta_generic_to_shared(As + r * (BK + 4) + c);
            cp_async16(dst, A + (long long)(bm + r) * lda + k0 + c);
        }
        if (TRANSB) {
#pragma unroll
            for (int i = tid; i < BN * BK / 4; i += 256) {
                int r = i / 8, c = (i % 8) * 4;
                uint32_t dst = (uint32_t)__cvta_generic_to_shared(Bs + r * (BK + 4) + c);
                cp_async16(dst, B + (long long)(bn + r) * ldb + k0 + c);
            }
        } else {
#pragma unroll
            for (int i = tid; i < BK * BN / 4; i += 256) {
                int r = i / 16, c = (i % 16) * 4;
                uint32_t dst = (uint32_t)__cvta_generic_to_shared(Bs + r * (BN + 4) + c);
                cp_async16(dst, B + (long long)(k0 + r) * ldb + bn + c);
            }
        }
    };

    load_tile(0, 0);
    cp_commit();

    for (int it = 0; it < nIter; it++) {
        if (it + 1 < nIter) {
            load_tile(it + 1, (it + 1) & 1);
            cp_commit();
            cp_wait<1>();
        } else {
            cp_wait<0>();
        }
        __syncthreads();

        const float* As = smemf + (it & 1) * STAGE_WORDS;
        const float* Bs = As + A_WORDS;

#pragma unroll
        for (int ks = 0; ks < BK / 8; ks++) {
            uint32_t ah[MI][4], bh[NI][2];
#pragma unroll
            for (int mi = 0; mi < MI; mi++) {
                const int r0 = wm0 + mi * 16 + g;
                const int c0 = ks * 8 + t;
                ah[mi][0] = f2tf32(As[(r0    ) * (BK + 4) + c0    ]);
                ah[mi][1] = f2tf32(As[(r0 + 8) * (BK + 4) + c0    ]);
                ah[mi][2] = f2tf32(As[(r0    ) * (BK + 4) + c0 + 4]);
                ah[mi][3] = f2tf32(As[(r0 + 8) * (BK + 4) + c0 + 4]);
            }
#pragma unroll
            for (int ni = 0; ni < NI; ni++) {
                const int n0 = wn0 + ni * 8 + g;
                if (TRANSB) {
                    bh[ni][0] = f2tf32(Bs[n0 * (BK + 4) + ks * 8 + t    ]);
                    bh[ni][1] = f2tf32(Bs[n0 * (BK + 4) + ks * 8 + t + 4]);
                } else {
                    bh[ni][0] = f2tf32(Bs[(ks * 8 + t    ) * (BN + 4) + n0]);
                    bh[ni][1] = f2tf32(Bs[(ks * 8 + t + 4) * (BN + 4) + n0]);
                }
            }
#pragma unroll
            for (int mi = 0; mi < MI; mi++)
#pragma unroll
                for (int ni = 0; ni < NI; ni++)
                    mma_tf32(acc[mi][ni], ah[mi], bh[ni]);
        }
        __syncthreads();
    }

#pragma unroll
    for (int mi = 0; mi < MI; mi++) {
#pragma unroll
        for (int ni = 0; ni < NI; ni++) {
            const long long row0 = bm + wm0 + mi * 16 + g;
            const long long col0 = bn + wn0 + ni * 8 + t * 2;
            float2 v0, v1;
            v0.x = alpha * acc[mi][ni][0];
            v0.y = alpha * acc[mi][ni][1];
            v1.x = alpha * acc[mi][ni][2];
            v1.y = alpha * acc[mi][ni][3];
            if (RES) {
                const float2 r0 = *(const float2*)(Res + row0 * ldc + col0);
                const float2 r1 = *(const float2*)(Res + (row0 + 8) * ldc + col0);
                v0.x += r0.x; v0.y += r0.y;
                v1.x += r1.x; v1.y += r1.y;
            }
            if (RND) {
                v0.x = __uint_as_float(f2tf32(v0.x));
                v0.y = __uint_as_float(f2tf32(v0.y));
                v1.x = __uint_as_float(f2tf32(v1.x));
                v1.y = __uint_as_float(f2tf32(v1.y));
            }
            *(float2*)(C + row0 * ldc + col0) = v0;
            *(float2*)(C + (row0 + 8) * ldc + col0) = v1;
        }
    }
}

// =================================================================
// Scores: bf16x3 compensated GEMM from compact hi/lo layout.
// exp values rounded to tf32-representable fp32 before store.
// =================================================================
#define SC_STRIDE 72   // bf16 elements per smem row (64 + 8 pad)

__global__ __launch_bounds__(256, 3) void scores_kernel(
    const __nv_bfloat16* __restrict__ qs, const __nv_bfloat16* __restrict__ ks_,
    float* __restrict__ attn, float* __restrict__ part)
{
    constexpr int BM = 128, BN = 64;
    constexpr int AT = BM * SC_STRIDE;
    constexpr int BT = BN * SC_STRIDE;

    extern __shared__ __nv_bfloat16 smemb[];
    __nv_bfloat16* Ah = smemb;
    __nv_bfloat16* Al = Ah + AT;
    __nv_bfloat16* Bh = Al + AT;
    __nv_bfloat16* Bl = Bh + BT;
    __shared__ float rowpart[2][BM];

    const int z = blockIdx.z;
    const int b = z >> 4, h = z & 15;
    const __nv_bfloat16* Aq = qs + (long long)b * S_LEN * LDHL + h * 128;
    const __nv_bfloat16* Bk = ks_ + (long long)b * S_LEN * LDHL + h * 128;
    float* C = attn + (long long)z * S_LEN * S_LEN;

    const int tid  = threadIdx.x;
    const int warp = tid >> 5;
    const int lane = tid & 31;
    const int g = lane >> 2;
    const int t = lane & 3;
    const int wm0 = (warp >> 1) * 32;
    const int wn0 = (warp & 1) * 32;
    const int wc  = warp & 1;
    const int bm = blockIdx.y * BM, bn = blockIdx.x * BN;

#pragma unroll
    for (int i = tid; i < BM * 8; i += 256) {
        const int r = i >> 3, c = (i & 7) * 8;
        const __nv_bfloat16* src = Aq + (long long)(bm + r) * LDHL + c;
        cp_async16((uint32_t)__cvta_generic_to_shared(Ah + r * SC_STRIDE + c), src);
        cp_async16((uint32_t)__cvta_generic_to_shared(Al + r * SC_STRIDE + c), src + 64);
    }
#pragma unroll
    for (int i = tid; i < BN * 8; i += 256) {
        const int r = i >> 3, c = (i & 7) * 8;
        const __nv_bfloat16* src = Bk + (long long)(bn + r) * LDHL + c;
        cp_async16((uint32_t)__cvta_generic_to_shared(Bh + r * SC_STRIDE + c), src);
        cp_async16((uint32_t)__cvta_generic_to_shared(Bl + r * SC_STRIDE + c), src + 64);
    }
    cp_commit();
    cp_wait<0>();
    __syncthreads();

    float acc[2][4][4];
#pragma unroll
    for (int i = 0; i < 2; i++)
#pragma unroll
        for (int j = 0; j < 4; j++)
#pragma unroll
            for (int r = 0; r < 4; r++) acc[i][j][r] = 0.0f;

#pragma unroll
    for (int ks = 0; ks < 4; ks++) {
        const int k0 = ks * 16;
        uint32_t a_h[2][4], a_l[2][4], b_h[4][2], b_l[4][2];
#pragma unroll
        for (int mi = 0; mi < 2; mi++) {
            const int r0 = wm0 + mi * 16 + g;
            const int o0 = r0 * SC_STRIDE + k0 + 2 * t;
            const int o1 = (r0 + 8) * SC_STRIDE + k0 + 2 * t;
            a_h[mi][0] = *(const uint32_t*)(Ah + o0);
            a_h[mi][1] = *(const uint32_t*)(Ah + o1);
            a_h[mi][2] = *(const uint32_t*)(Ah + o0 + 8);
            a_h[mi][3] = *(const uint32_t*)(Ah + o1 + 8);
            a_l[mi][0] = *(const uint32_t*)(Al + o0);
            a_l[mi][1] = *(const uint32_t*)(Al + o1);
            a_l[mi][2] = *(const uint32_t*)(Al + o0 + 8);
            a_l[mi][3] = *(const uint32_t*)(Al + o1 + 8);
        }
#pragma unroll
        for (int ni = 0; ni < 4; ni++) {
            const int n0 = wn0 + ni * 8 + g;
            const int ob = n0 * SC_STRIDE + k0 + 2 * t;
            b_h[ni][0] = *(const uint32_t*)(Bh + ob);
            b_h[ni][1] = *(const uint32_t*)(Bh + ob + 8);
            b_l[ni][0] = *(const uint32_t*)(Bl + ob);
            b_l[ni][1] = *(const uint32_t*)(Bl + ob + 8);
        }
#pragma unroll
        for (int mi = 0; mi < 2; mi++)
#pragma unroll
            for (int ni = 0; ni < 4; ni++) {
                mma_bf16(acc[mi][ni], a_l[mi], b_h[ni]);
                mma_bf16(acc[mi][ni], a_h[mi], b_l[ni]);
                mma_bf16(acc[mi][ni], a_h[mi], b_h[ni]);
            }
    }

    float rsum[2][2] = {{0.f, 0.f}, {0.f, 0.f}};
#pragma unroll
    for (int mi = 0; mi < 2; mi++) {
#pragma unroll
        for (int ni = 0; ni < 4; ni++) {
#pragma unroll
            for (int r = 0; r < 4; r++) {
                float e = __expf(0.125f * acc[mi][ni][r]);
                acc[mi][ni][r] = __uint_as_float(f2tf32(e));   // tf32-representable
            }
            rsum[mi][0] += acc[mi][ni][0] + acc[mi][ni][1];
            rsum[mi][1] += acc[mi][ni][2] + acc[mi][ni][3];

            const long long row0 = bm + wm0 + mi * 16 + g;
            const long long col0 = bn + wn0 + ni * 8 + t * 2;
            float2 v0 = {acc[mi][ni][0], acc[mi][ni][1]};
            float2 v1 = {acc[mi][ni][2], acc[mi][ni][3]};
            *(float2*)(C + row0 * S_LEN + col0) = v0;
            *(float2*)(C + (row0 + 8) * S_LEN + col0) = v1;
        }
    }
#pragma unroll
    for (int mi = 0; mi < 2; mi++)
#pragma unroll
        for (int s = 0; s < 2; s++) {
            float v = rsum[mi][s];
            v += __shfl_xor_sync(0xffffffffu, v, 1);
            v += __shfl_xor_sync(0xffffffffu, v, 2);
            if (t == 0) rowpart[wc][wm0 + mi * 16 + s * 8 + g] = v;
        }
    __syncthreads();
    if (tid < BM) {
        float p = rowpart[0][tid] + rowpart[1][tid];
        part[((long long)z * S_LEN + bm + tid) * NCHUNK + blockIdx.x] = p;
    }
}

// =================================================================
// PV kernel: inputs pre-rounded to tf32 -> zero-ALU mainloop.
// Normalizes attn in place; out = (e@V)/s.
// =================================================================
__global__ __launch_bounds__(256, 2) void pv_kernel(
    float* __restrict__ attn, const float* __restrict__ vp,
    float* __restrict__ ao, const float* __restrict__ part)
{
    constexpr int BM = 128, BN = 64, BK = 32;
    constexpr int A_WORDS = BM * (BK + 4);
    constexpr int B_WORDS = BK * (BN + 4);
    constexpr int STAGE_WORDS = A_WORDS + B_WORDS;

    extern __shared__ float smemf[];
    __shared__ float sInv[BM];

    const int z = blockIdx.z;
    const int b = z >> 4, h = z & 15;
    float* A = attn + (long long)z * S_LEN * S_LEN;
    const float* B = vp + (long long)b * S_LEN * DMODEL + h * DHEAD;
    float* C = ao + (long long)b * S_LEN * DMODEL + h * DHEAD;

    const int tid  = threadIdx.x;
    const int warp = tid >> 5;
    const int lane = tid & 31;
    const int g = lane >> 2;
    const int t = lane & 3;
    const int wm0 = (warp >> 1) * 32;
    const int wn0 = (warp & 1) * 32;
    const int bm = blockIdx.y * BM;

    if (tid < BM) {
        const float* p = part + ((long long)z * S_LEN + bm + tid) * NCHUNK;
        float s = 0.0f;
#pragma unroll
        for (int j = 0; j < NCHUNK; j++) s += p[j];
        sInv[tid] = 1.0f / s;
    }

    float acc[2][4][4];
#pragma unroll
    for (int i = 0; i < 2; i++)
#pragma unroll
        for (int j = 0; j < 4; j++)
#pragma unroll
            for (int r = 0; r < 4; r++) acc[i][j][r] = 0.0f;

    auto load_tile = [&](int it, int stage) {
        float* As = smemf + stage * STAGE_WORDS;
        float* Bs = As + A_WORDS;
        const int k0 = it * BK;
#pragma unroll
        for (int i = tid; i < BM * BK / 4; i += 256) {
            int r = i / 8, c = (i % 8) * 4;
            uint32_t dst = (uint32_t)__cvta_generic_to_shared(As + r * (BK + 4) + c);
            cp_async16(dst, A + (long long)(bm + r) * S_LEN + k0 + c);
        }
#pragma unroll
        for (int i = tid; i < BK * BN / 4; i += 256) {
            int r = i / 16, c = (i % 16) * 4;
            uint32_t dst = (uint32_t)__cvta_generic_to_shared(Bs + r * (BN + 4) + c);
            cp_async16(dst, B + (long long)(k0 + r) * DMODEL + c);
        }
    };

    load_tile(0, 0);
    cp_commit();

    const int nIter = S_LEN / BK;   // 64
    for (int it = 0; it < nIter; it++) {
        if (it + 1 < nIter) {
            load_tile(it + 1, (it + 1) & 1);
            cp_commit();
            cp_wait<1>();
        } else {
            cp_wait<0>();
        }
        __syncthreads();

        const float* As = smemf + (it & 1) * STAGE_WORDS;
        const float* Bs = As + A_WORDS;

        // write normalized attn for this tile (data already in smem)
#pragma unroll
        for (int i = tid; i < BM * BK; i += 256) {
            const int r = i >> 5, c = i & 31;
            A[(long long)(bm + r) * S_LEN + it * BK + c] = As[r * (BK + 4) + c] * sInv[r];
        }

#pragma unroll
        for (int ks = 0; ks < BK / 8; ks++) {
            uint32_t ah[2][4], bh[4][2];
#pragma unroll
            for (int mi = 0; mi < 2; mi++) {
                const int r0 = wm0 + mi * 16 + g;
                const int c0 = ks * 8 + t;
                // values already tf32-representable: pass bits directly
                ah[mi][0] = __float_as_uint(As[(r0    ) * (BK + 4) + c0    ]);
                ah[mi][1] = __float_as_uint(As[(r0 + 8) * (BK + 4) + c0    ]);
                ah[mi][2] = __float_as_uint(As[(r0    ) * (BK + 4) + c0 + 4]);
                ah[mi][3] = __float_as_uint(As[(r0 + 8) * (BK + 4) + c0 + 4]);
            }
#pragma unroll
            for (int ni = 0; ni < 4; ni++) {
                const int n0 = wn0 + ni * 8 + g;
                bh[ni][0] = __float_as_uint(Bs[(ks * 8 + t    ) * (BN + 4) + n0]);
                bh[ni][1] = __float_as_uint(Bs[(ks * 8 + t + 4) * (BN + 4) + n0]);
            }
#pragma unroll
            for (int mi = 0; mi < 2; mi++)
#pragma unroll
                for (int ni = 0; ni < 4; ni++)
                    mma_tf32(acc[mi][ni], ah[mi], bh[ni]);
        }
        __syncthreads();
    }

#pragma unroll
    for (int mi = 0; mi < 2; mi++) {
#pragma unroll
        for (int ni = 0; ni < 4; ni++) {
            const int rl0 = wm0 + mi * 16 + g;
            const long long row0 = bm + rl0;
            const long long col0 = wn0 + ni * 8 + t * 2;
            float2 v0, v1;
            v0.x = acc[mi][ni][0] * sInv[rl0];
            v0.y = acc[mi][ni][1] * sInv[rl0];
            v1.x = acc[mi][ni][2] * sInv[rl0 + 8];
            v1.y = acc[mi][ni][3] * sInv[rl0 + 8];
            *(float2*)(C + row0 * DMODEL + col0) = v0;
            *(float2*)(C + (row0 + 8) * DMODEL + col0) = v1;
        }
    }
}

// =================================================================
// In-place LayerNorm over rows of length DMODEL (1024). 256 threads.
// =================================================================
__global__ __launch_bounds__(256) void ln_kernel(float* __restrict__ x,
                                                 const float* __restrict__ gamma,
                                                 const float* __restrict__ beta)
{
    float* row = x + (size_t)blockIdx.x * DMODEL;
    const int tid = threadIdx.x;
    __shared__ float ssum[8], ssq[8];

    float v[4];
    float s = 0.0f, sq = 0.0f;
#pragma unroll
    for (int j = 0; j < 4; j++) {
        v[j] = row[tid + j * 256];
        s += v[j];
        sq += v[j] * v[j];
    }
#pragma unroll
    for (int o = 16; o > 0; o >>= 1) {
        s  += __shfl_xor_sync(0xffffffffu, s, o);
        sq += __shfl_xor_sync(0xffffffffu, sq, o);
    }
    if ((tid & 31) == 0) { ssum[tid >> 5] = s; ssq[tid >> 5] = sq; }
    __syncthreads();
    s = 0.0f; sq = 0.0f;
#pragma unroll
    for (int j = 0; j < 8; j++) { s += ssum[j]; sq += ssq[j]; }

    const float mu = s * (1.0f / DMODEL);
    const float var = sq * (1.0f / DMODEL) - mu * mu;
    const float rstd = rsqrtf(var + 1e-6f);
#pragma unroll
    for (int j = 0; j < 4; j++) {
        const int c = tid + j * 256;
        row[c] = (v[j] - mu) * rstd * gamma[c] + beta[c];
    }
}

// =================================================================
static constexpr int GEMM_SMEM = 2 * (128 * 36 + 64 * 36) * 4;         // 55296 B
static constexpr int PROJ_SMEM = 2 * (2 * 128 * 40 + 2 * 64 * 40) * 2; // 61440 B
static constexpr int SC_SMEM   = (2 * 128 * 72 + 2 * 64 * 72) * 2;     // 55296 B
static constexpr int PV_SMEM   = 2 * (128 * 36 + 32 * 68) * 4;         // 54272 B

extern "C" void kernel_launch(void* const* d_in, const int* in_sizes, int n_in,
                              void* d_out, int out_size)
{
    const float* q     = (const float*)d_in[0];
    const float* k     = (const float*)d_in[1];
    const float* v     = (const float*)d_in[2];
    const float* w_q   = (const float*)d_in[3];
    const float* w_k   = (const float*)d_in[4];
    const float* w_v   = (const float*)d_in[5];
    const float* w_fc  = (const float*)d_in[6];
    const float* gamma = (const float*)d_in[7];
    const float* beta  = (const float*)d_in[8];

    __nv_bfloat16 *qs, *ks_, *q2, *k2, *wq2, *wk2;
    float *vp, *ao, *part;
    cudaGetSymbolAddress((void**)&qs, g_qs);
    cudaGetSymbolAddress((void**)&ks_, g_ks);
    cudaGetSymbolAddress((void**)&q2, g_q2);
    cudaGetSymbolAddress((void**)&k2, g_k2);
    cudaGetSymbolAddress((void**)&wq2, g_wq2);
    cudaGetSymbolAddress((void**)&wk2, g_wk2);
    cudaGetSymbolAddress((void**)&vp, g_vp);
    cudaGetSymbolAddress((void**)&ao, g_ao);
    cudaGetSymbolAddress((void**)&part, g_part);

    float* out  = (float*)d_out;
    float* attn = out + (size_t)MROWS * DMODEL;   // [B, H, Sq, Sk] fp32

    cudaFuncSetAttribute(proj_bf16_kernel,
                         cudaFuncAttributeMaxDynamicSharedMemorySize, PROJ_SMEM);
    cudaFuncSetAttribute(gemm_tc<true,false,true>,
                         cudaFuncAttributeMaxDynamicSharedMemorySize, GEMM_SMEM);
    cudaFuncSetAttribute(gemm_tc<true,true,false>,
                         cudaFuncAttributeMaxDynamicSharedMemorySize, GEMM_SMEM);
    cudaFuncSetAttribute(scores_kernel,
                         cudaFuncAttributeMaxDynamicSharedMemorySize, SC_SMEM);
    cudaFuncSetAttribute(pv_kernel,
                         cudaFuncAttributeMaxDynamicSharedMemorySize, PV_SMEM);

    dim3 blk(256);
    const int actBlocks = MROWS * (DMODEL / 4) / 256;   // 8192
    const int wBlocks   = DMODEL * (DMODEL / 4) / 256;  // 1024

    // --- split q, k, w_q, w_k into bf16 hi|lo planes ---
    split_planes<<<actBlocks, blk>>>(q, q2, MROWS);
    split_planes<<<actBlocks, blk>>>(k, k2, MROWS);
    split_planes<<<wBlocks, blk>>>(w_q, wq2, DMODEL);
    split_planes<<<wBlocks, blk>>>(w_k, wk2, DMODEL);

    // --- Q/K projections: zero-ALU bf16x3 GEMM from planes ---
    {
        dim3 g(DMODEL / 64, MROWS / 128, 1);
        proj_bf16_kernel<<<g, blk, PROJ_SMEM>>>(q2, wq2, qs);
        proj_bf16_kernel<<<g, blk, PROJ_SMEM>>>(k2, wk2, ks_);
    }
    // --- V projection (single tf32, output rounded to tf32) ---
    {
        dim3 g(DMODEL / 64, MROWS / 128, 1);
        gemm_tc<true,false,true><<<g, blk, GEMM_SMEM>>>(
            v, DMODEL, w_v, DMODEL, vp, DMODEL, DMODEL, 1.0f, nullptr);
    }

    // --- scores (bf16x3) + exp (tf32-rounded) + partials ---
    {
        dim3 g(S_LEN / 64, S_LEN / 128, NZ);
        scores_kernel<<<g, blk, SC_SMEM>>>(qs, ks_, attn, part);
    }

    // --- PV (zero-ALU tf32) + in-place softmax normalization ---
    {
        dim3 g(1, S_LEN / 128, NZ);
        pv_kernel<<<g, blk, PV_SMEM>>>(attn, vp, ao, part);
    }

    // --- fc + residual (single tf32) ---
    {
        dim3 g(DMODEL / 64, MROWS / 128, 1);
        gemm_tc<true,true,false><<<g, blk, GEMM_SMEM>>>(
            ao, DMODEL, w_fc, DMODEL, out, DMODEL, DMODEL, 1.0f, q);
    }

    // --- layernorm in place ---
    ln_kernel<<<MROWS, blk>>>(out, gamma, beta);
}

// round 13
// speedup vs baseline: 1.0810x; 1.0106x over previous
#include <cuda_runtime.h>
#include <cuda_bf16.h>
#include <math.h>
#include <stdint.h>

#define S_LEN  2048
#define BATCH  4
#define NHEAD  16
#define DMODEL 1024
#define DHEAD  64
#define MROWS  (BATCH * S_LEN)   // 8192
#define NZ     (BATCH * NHEAD)   // 64
#define NCHUNK 32                // scores grid.x chunks
#define LDHL   (NHEAD * 128)     // 2048 bf16 per row: per head hi(64)|lo(64)
#define LD2    (2 * DMODEL)      // 2048: hi|lo plane row stride

// ---------------- scratch (no allocations allowed) ----------------
__device__ __nv_bfloat16 g_qs[(size_t)MROWS * LDHL];  // per-head compact q hi|lo
__device__ __nv_bfloat16 g_ks[(size_t)MROWS * LDHL];  // per-head compact k hi|lo
__device__ __nv_bfloat16 g_q2[(size_t)MROWS * LD2];   // q input planes [row][hi|lo]
__device__ __nv_bfloat16 g_k2[(size_t)MROWS * LD2];   // k input planes
__device__ __nv_bfloat16 g_wq2[(size_t)DMODEL * LD2]; // w_q planes [out][hi|lo]
__device__ __nv_bfloat16 g_wk2[(size_t)DMODEL * LD2]; // w_k planes
__device__ float g_vp[(size_t)MROWS * DMODEL];        // tf32-rounded V proj
__device__ float g_ao[(size_t)MROWS * DMODEL];        // tf32-rounded PV out
__device__ float g_wf[(size_t)DMODEL * DMODEL];       // tf32-rounded w_fc
__device__ float g_part[(size_t)NZ * S_LEN * NCHUNK];

// ---------------- helpers ----------------
__device__ __forceinline__ void mma_tf32(float c[4], const uint32_t a[4], const uint32_t b[2]) {
    asm volatile(
        "mma.sync.aligned.m16n8k8.row.col.f32.tf32.tf32.f32 "
        "{%0,%1,%2,%3}, {%4,%5,%6,%7}, {%8,%9}, {%0,%1,%2,%3};\n"
        : "+f"(c[0]), "+f"(c[1]), "+f"(c[2]), "+f"(c[3])
        : "r"(a[0]), "r"(a[1]), "r"(a[2]), "r"(a[3]), "r"(b[0]), "r"(b[1]));
}
__device__ __forceinline__ void mma_bf16(float c[4], const uint32_t a[4], const uint32_t b[2]) {
    asm volatile(
        "mma.sync.aligned.m16n8k16.row.col.f32.bf16.bf16.f32 "
        "{%0,%1,%2,%3}, {%4,%5,%6,%7}, {%8,%9}, {%0,%1,%2,%3};\n"
        : "+f"(c[0]), "+f"(c[1]), "+f"(c[2]), "+f"(c[3])
        : "r"(a[0]), "r"(a[1]), "r"(a[2]), "r"(a[3]), "r"(b[0]), "r"(b[1]));
}
__device__ __forceinline__ uint32_t f2tf32(float x) {
    uint32_t r;
    asm("cvt.rna.tf32.f32 %0, %1;\n" : "=r"(r) : "f"(x));
    return r;
}
__device__ __forceinline__ void cp_async16(uint32_t smem_addr, const void* gptr) {
    asm volatile("cp.async.cg.shared.global [%0], [%1], 16;\n" :: "r"(smem_addr), "l"(gptr));
}
__device__ __forceinline__ void cp_commit() { asm volatile("cp.async.commit_group;\n"); }
template <int N> __device__ __forceinline__ void cp_wait() {
    asm volatile("cp.async.wait_group %0;\n" :: "n"(N));
}

// =================================================================
// Split fp32 -> bf16 hi|lo planes.
// =================================================================
__global__ __launch_bounds__(256) void split_planes(
    const float* __restrict__ x, __nv_bfloat16* __restrict__ o, int rows)
{
    const int n4 = rows * (DMODEL / 4);
    int idx = blockIdx.x * 256 + threadIdx.x;
    if (idx >= n4) return;
    const int row = idx / (DMODEL / 4);
    const int c4  = idx % (DMODEL / 4);
    const float4 v = ((const float4*)x)[idx];
    __nv_bfloat16 h[4], l[4];
    h[0] = __float2bfloat16(v.x); l[0] = __float2bfloat16(v.x - __bfloat162float(h[0]));
    h[1] = __float2bfloat16(v.y); l[1] = __float2bfloat16(v.y - __bfloat162float(h[1]));
    h[2] = __float2bfloat16(v.z); l[2] = __float2bfloat16(v.z - __bfloat162float(h[2]));
    h[3] = __float2bfloat16(v.w); l[3] = __float2bfloat16(v.w - __bfloat162float(h[3]));
    *(uint2*)(o + (size_t)row * LD2 + c4 * 4)          = *(const uint2*)h;
    *(uint2*)(o + (size_t)row * LD2 + DMODEL + c4 * 4) = *(const uint2*)l;
}

// =================================================================
// Round fp32 array to tf32-representable fp32 (for zero-ALU GEMMs).
// =================================================================
__global__ __launch_bounds__(256) void round_tf32_kernel(
    const float* __restrict__ x, float* __restrict__ o, int n4)
{
    int idx = blockIdx.x * 256 + threadIdx.x;
    if (idx >= n4) return;
    float4 v = ((const float4*)x)[idx];
    v.x = __uint_as_float(f2tf32(v.x));
    v.y = __uint_as_float(f2tf32(v.y));
    v.z = __uint_as_float(f2tf32(v.z));
    v.w = __uint_as_float(f2tf32(v.w));
    ((float4*)o)[idx] = v;
}

// =================================================================
// Q/K projection: zero-ALU bf16x3 GEMM over precomputed planes.
// Epilogue writes compact per-head bf16 hi|lo layout.
// =================================================================
#define PS 40   // bf16 smem row stride (32 + 8 pad)

__global__ __launch_bounds__(256, 2) void proj_bf16_kernel(
    const __nv_bfloat16* __restrict__ A2,
    const __nv_bfloat16* __restrict__ B2,
    __nv_bfloat16* __restrict__ C)
{
    constexpr int BM = 128, BN = 64, BK = 32;
    constexpr int APL = BM * PS;
    constexpr int BPL = BN * PS;
    constexpr int STAGE = 2 * APL + 2 * BPL;

    extern __shared__ __nv_bfloat16 smemb[];

    const int tid  = threadIdx.x;
    const int warp = tid >> 5;
    const int lane = tid & 31;
    const int g = lane >> 2;
    const int t = lane & 3;
    const int wm0 = (warp >> 1) * 32;
    const int wn0 = (warp & 1) * 32;
    const int bm = blockIdx.y * BM, bn = blockIdx.x * BN;

    float acc[2][4][4];
#pragma unroll
    for (int i = 0; i < 2; i++)
#pragma unroll
        for (int j = 0; j < 4; j++)
#pragma unroll
            for (int r = 0; r < 4; r++) acc[i][j][r] = 0.0f;

    auto load_tile = [&](int it, int stage) {
        __nv_bfloat16* Ah = smemb + stage * STAGE;
        __nv_bfloat16* Al = Ah + APL;
        __nv_bfloat16* Bh = Al + APL;
        __nv_bfloat16* Bl = Bh + BPL;
        const int k0 = it * BK;
#pragma unroll
        for (int i = tid; i < BM * 4; i += 256) {
            const int r = i >> 2, c = (i & 3) * 8;
            const __nv_bfloat16* src = A2 + (size_t)(bm + r) * LD2 + k0 + c;
            cp_async16((uint32_t)__cvta_generic_to_shared(Ah + r * PS + c), src);
            cp_async16((uint32_t)__cvta_generic_to_shared(Al + r * PS + c), src + DMODEL);
        }
#pragma unroll
        for (int i = tid; i < BN * 4; i += 256) {
            const int r = i >> 2, c = (i & 3) * 8;
            const __nv_bfloat16* src = B2 + (size_t)(bn + r) * LD2 + k0 + c;
            cp_async16((uint32_t)__cvta_generic_to_shared(Bh + r * PS + c), src);
            cp_async16((uint32_t)__cvta_generic_to_shared(Bl + r * PS + c), src + DMODEL);
        }
    };

    load_tile(0, 0);
    cp_commit();

    constexpr int nIter = DMODEL / BK;   // 32
    for (int it = 0; it < nIter; it++) {
        if (it + 1 < nIter) {
            load_tile(it + 1, (it + 1) & 1);
            cp_commit();
            cp_wait<1>();
        } else {
            cp_wait<0>();
        }
        __syncthreads();

        const __nv_bfloat16* Ah = smemb + (it & 1) * STAGE;
        const __nv_bfloat16* Al = Ah + APL;
        const __nv_bfloat16* Bh = Al + APL;
        const __nv_bfloat16* Bl = Bh + BPL;

#pragma unroll
        for (int ks = 0; ks < 2; ks++) {
            const int k0 = ks * 16;
            uint32_t a_h[2][4], a_l[2][4], b_h[4][2], b_l[4][2];
#pragma unroll
            for (int mi = 0; mi < 2; mi++) {
                const int r0 = wm0 + mi * 16 + g;
                const int o0 = r0 * PS + k0 + 2 * t;
                const int o1 = (r0 + 8) * PS + k0 + 2 * t;
                a_h[mi][0] = *(const uint32_t*)(Ah + o0);
                a_h[mi][1] = *(const uint32_t*)(Ah + o1);
                a_h[mi][2] = *(const uint32_t*)(Ah + o0 + 8);
                a_h[mi][3] = *(const uint32_t*)(Ah + o1 + 8);
                a_l[mi][0] = *(const uint32_t*)(Al + o0);
                a_l[mi][1] = *(const uint32_t*)(Al + o1);
                a_l[mi][2] = *(const uint32_t*)(Al + o0 + 8);
                a_l[mi][3] = *(const uint32_t*)(Al + o1 + 8);
            }
#pragma unroll
            for (int ni = 0; ni < 4; ni++) {
                const int n0 = wn0 + ni * 8 + g;
                const int ob = n0 * PS + k0 + 2 * t;
                b_h[ni][0] = *(const uint32_t*)(Bh + ob);
                b_h[ni][1] = *(const uint32_t*)(Bh + ob + 8);
                b_l[ni][0] = *(const uint32_t*)(Bl + ob);
                b_l[ni][1] = *(const uint32_t*)(Bl + ob + 8);
            }
#pragma unroll
            for (int mi = 0; mi < 2; mi++)
#pragma unroll
                for (int ni = 0; ni < 4; ni++) {
                    mma_bf16(acc[mi][ni], a_l[mi], b_h[ni]);
                    mma_bf16(acc[mi][ni], a_h[mi], b_l[ni]);
                    mma_bf16(acc[mi][ni], a_h[mi], b_h[ni]);
                }
        }
        __syncthreads();
    }

    // ---- epilogue: compact per-head bf16 hi|lo ----
#pragma unroll
    for (int mi = 0; mi < 2; mi++) {
#pragma unroll
        for (int ni = 0; ni < 4; ni++) {
            const long long row0 = bm + wm0 + mi * 16 + g;
            const long long col0 = bn + wn0 + ni * 8 + t * 2;
#pragma unroll
            for (int e = 0; e < 4; e++) {
                const long long row = row0 + (e >> 1) * 8;
                const int col = (int)col0 + (e & 1);
                const float val = acc[mi][ni][e];
                const __nv_bfloat16 hi = __float2bfloat16(val);
                const __nv_bfloat16 lo = __float2bfloat16(val - __bfloat162float(hi));
                const long long base = row * LDHL + (col >> 6) * 128 + (col & 63);
                C[base     ] = hi;
                C[base + 64] = lo;
            }
        }
    }
}

// =================================================================
// Generic tensor-core tf32 GEMM (V proj, fc). BM=128, BN=64, BK=32.
// RND: epilogue rounds output to tf32-representable fp32.
// PT:  inputs already tf32-representable -> zero-ALU (bit pass).
// =================================================================
template <bool TRANSB, bool RES, bool RND, bool PT>
__global__ __launch_bounds__(256, 2) void gemm_tc(
    const float* __restrict__ A, int lda,
    const float* __restrict__ B, int ldb,
    float* __restrict__ C, int ldc,
    int K, float alpha, const float* __restrict__ Res)
{
    constexpr int BM = 128, BN = 64, BK = 32;
    constexpr int MI = 2, NI = 4;
    constexpr int A_WORDS = BM * (BK + 4);
    constexpr int B_WORDS = TRANSB ? BN * (BK + 4) : BK * (BN + 4);
    constexpr int STAGE_WORDS = A_WORDS + B_WORDS;

    extern __shared__ float smemf[];

    const int tid  = threadIdx.x;
    const int warp = tid >> 5;
    const int lane = tid & 31;
    const int g = lane >> 2;
    const int t = lane & 3;
    const int wm0 = (warp >> 1) * 32;
    const int wn0 = (warp & 1) * 32;
    const int bm = blockIdx.y * BM, bn = blockIdx.x * BN;

    float acc[MI][NI][4];
#pragma unroll
    for (int i = 0; i < MI; i++)
#pragma unroll
        for (int j = 0; j < NI; j++)
#pragma unroll
            for (int r = 0; r < 4; r++) acc[i][j][r] = 0.0f;

    const int nIter = K / BK;

    auto load_tile = [&](int it, int stage) {
        float* As = smemf + stage * STAGE_WORDS;
        float* Bs = As + A_WORDS;
        const int k0 = it * BK;
#pragma unroll
        for (int i = tid; i < BM * BK / 4; i += 256) {
            int r = i / 8, c = (i % 8) * 4;
            uint32_t dst = (uint32_t)__cvta_generic_to_shared(As + r * (BK + 4) + c);
            cp_async16(dst, A + (long long)(bm + r) * lda + k0 + c);
        }
        if (TRANSB) {
#pragma unroll
            for (int i = tid; i < BN * BK / 4; i += 256) {
                int r = i / 8, c = (i % 8) * 4;
                uint32_t dst = (uint32_t)__cvta_generic_to_shared(Bs + r * (BK + 4) + c);
                cp_async16(dst, B + (long long)(bn + r) * ldb + k0 + c);
            }
        } else {
#pragma unroll
            for (int i = tid; i < BK * BN / 4; i += 256) {
                int r = i / 16, c = (i % 16) * 4;
                uint32_t dst = (uint32_t)__cvta_generic_to_shared(Bs + r * (BN + 4) + c);
                cp_async16(dst, B + (long long)(k0 + r) * ldb + bn + c);
            }
        }
    };

    load_tile(0, 0);
    cp_commit();

    for (int it = 0; it < nIter; it++) {
        if (it + 1 < nIter) {
            load_tile(it + 1, (it + 1) & 1);
            cp_commit();
            cp_wait<1>();
        } else {
            cp_wait<0>();
        }
        __syncthreads();

        const float* As = smemf + (it & 1) * STAGE_WORDS;
        const float* Bs = As + A_WORDS;

#pragma unroll
        for (int ks = 0; ks < BK / 8; ks++) {
            uint32_t ah[MI][4], bh[NI][2];
#pragma unroll
            for (int mi = 0; mi < MI; mi++) {
                const int r0 = wm0 + mi * 16 + g;
                const int c0 = ks * 8 + t;
                if (PT) {
                    ah[mi][0] = __float_as_uint(As[(r0    ) * (BK + 4) + c0    ]);
                    ah[mi][1] = __float_as_uint(As[(r0 + 8) * (BK + 4) + c0    ]);
                    ah[mi][2] = __float_as_uint(As[(r0    ) * (BK + 4) + c0 + 4]);
                    ah[mi][3] = __float_as_uint(As[(r0 + 8) * (BK + 4) + c0 + 4]);
                } else {
                    ah[mi][0] = f2tf32(As[(r0    ) * (BK + 4) + c0    ]);
                    ah[mi][1] = f2tf32(As[(r0 + 8) * (BK + 4) + c0    ]);
                    ah[mi][2] = f2tf32(As[(r0    ) * (BK + 4) + c0 + 4]);
                    ah[mi][3] = f2tf32(As[(r0 + 8) * (BK + 4) + c0 + 4]);
                }
            }
#pragma unroll
            for (int ni = 0; ni < NI; ni++) {
                const int n0 = wn0 + ni * 8 + g;
                float b0, b1;
                if (TRANSB) {
                    b0 = Bs[n0 * (BK + 4) + ks * 8 + t    ];
                    b1 = Bs[n0 * (BK + 4) + ks * 8 + t + 4];
                } else {
                    b0 = Bs[(ks * 8 + t    ) * (BN + 4) + n0];
                    b1 = Bs[(ks * 8 + t + 4) * (BN + 4) + n0];
                }
                if (PT) {
                    bh[ni][0] = __float_as_uint(b0);
                    bh[ni][1] = __float_as_uint(b1);
                } else {
                    bh[ni][0] = f2tf32(b0);
                    bh[ni][1] = f2tf32(b1);
                }
            }
#pragma unroll
            for (int mi = 0; mi < MI; mi++)
#pragma unroll
                for (int ni = 0; ni < NI; ni++)
                    mma_tf32(acc[mi][ni], ah[mi], bh[ni]);
        }
        __syncthreads();
    }

#pragma unroll
    for (int mi = 0; mi < MI; mi++) {
#pragma unroll
        for (int ni = 0; ni < NI; ni++) {
            const long long row0 = bm + wm0 + mi * 16 + g;
            const long long col0 = bn + wn0 + ni * 8 + t * 2;
            float2 v0, v1;
            v0.x = alpha * acc[mi][ni][0];
            v0.y = alpha * acc[mi][ni][1];
            v1.x = alpha * acc[mi][ni][2];
            v1.y = alpha * acc[mi][ni][3];
            if (RES) {
                const float2 r0 = *(const float2*)(Res + row0 * ldc + col0);
                const float2 r1 = *(const float2*)(Res + (row0 + 8) * ldc + col0);
                v0.x += r0.x; v0.y += r0.y;
                v1.x += r1.x; v1.y += r1.y;
            }
            if (RND) {
                v0.x = __uint_as_float(f2tf32(v0.x));
                v0.y = __uint_as_float(f2tf32(v0.y));
                v1.x = __uint_as_float(f2tf32(v1.x));
                v1.y = __uint_as_float(f2tf32(v1.y));
            }
            *(float2*)(C + row0 * ldc + col0) = v0;
            *(float2*)(C + (row0 + 8) * ldc + col0) = v1;
        }
    }
}

// =================================================================
// Scores: bf16x3 compensated GEMM from compact hi/lo layout.
// exp values rounded to tf32-representable fp32 before store.
// =================================================================
#define SC_STRIDE 72   // bf16 elements per smem row (64 + 8 pad)

__global__ __launch_bounds__(256, 3) void scores_kernel(
    const __nv_bfloat16* __restrict__ qs, const __nv_bfloat16* __restrict__ ks_,
    float* __restrict__ attn, float* __restrict__ part)
{
    constexpr int BM = 128, BN = 64;
    constexpr int AT = BM * SC_STRIDE;
    constexpr int BT = BN * SC_STRIDE;

    extern __shared__ __nv_bfloat16 smemb[];
    __nv_bfloat16* Ah = smemb;
    __nv_bfloat16* Al = Ah + AT;
    __nv_bfloat16* Bh = Al + AT;
    __nv_bfloat16* Bl = Bh + BT;
    __shared__ float rowpart[2][BM];

    const int z = blockIdx.z;
    const int b = z >> 4, h = z & 15;
    const __nv_bfloat16* Aq = qs + (long long)b * S_LEN * LDHL + h * 128;
    const __nv_bfloat16* Bk = ks_ + (long long)b * S_LEN * LDHL + h * 128;
    float* C = attn + (long long)z * S_LEN * S_LEN;

    const int tid  = threadIdx.x;
    const int warp = tid >> 5;
    const int lane = tid & 31;
    const int g = lane >> 2;
    const int t = lane & 3;
    const int wm0 = (warp >> 1) * 32;
    const int wn0 = (warp & 1) * 32;
    const int wc  = warp & 1;
    const int bm = blockIdx.y * BM, bn = blockIdx.x * BN;

#pragma unroll
    for (int i = tid; i < BM * 8; i += 256) {
        const int r = i >> 3, c = (i & 7) * 8;
        const __nv_bfloat16* src = Aq + (long long)(bm + r) * LDHL + c;
        cp_async16((uint32_t)__cvta_generic_to_shared(Ah + r * SC_STRIDE + c), src);
        cp_async16((uint32_t)__cvta_generic_to_shared(Al + r * SC_STRIDE + c), src + 64);
    }
#pragma unroll
    for (int i = tid; i < BN * 8; i += 256) {
        const int r = i >> 3, c = (i & 7) * 8;
        const __nv_bfloat16* src = Bk + (long long)(bn + r) * LDHL + c;
        cp_async16((uint32_t)__cvta_generic_to_shared(Bh + r * SC_STRIDE + c), src);
        cp_async16((uint32_t)__cvta_generic_to_shared(Bl + r * SC_STRIDE + c), src + 64);
    }
    cp_commit();
    cp_wait<0>();
    __syncthreads();

    float acc[2][4][4];
#pragma unroll
    for (int i = 0; i < 2; i++)
#pragma unroll
        for (int j = 0; j < 4; j++)
#pragma unroll
            for (int r = 0; r < 4; r++) acc[i][j][r] = 0.0f;

#pragma unroll
    for (int ks = 0; ks < 4; ks++) {
        const int k0 = ks * 16;
        uint32_t a_h[2][4], a_l[2][4], b_h[4][2], b_l[4][2];
#pragma unroll
        for (int mi = 0; mi < 2; mi++) {
            const int r0 = wm0 + mi * 16 + g;
            const int o0 = r0 * SC_STRIDE + k0 + 2 * t;
            const int o1 = (r0 + 8) * SC_STRIDE + k0 + 2 * t;
            a_h[mi][0] = *(const uint32_t*)(Ah + o0);
            a_h[mi][1] = *(const uint32_t*)(Ah + o1);
            a_h[mi][2] = *(const uint32_t*)(Ah + o0 + 8);
            a_h[mi][3] = *(const uint32_t*)(Ah + o1 + 8);
            a_l[mi][0] = *(const uint32_t*)(Al + o0);
            a_l[mi][1] = *(const uint32_t*)(Al + o1);
            a_l[mi][2] = *(const uint32_t*)(Al + o0 + 8);
            a_l[mi][3] = *(const uint32_t*)(Al + o1 + 8);
        }
#pragma unroll
        for (int ni = 0; ni < 4; ni++) {
            const int n0 = wn0 + ni * 8 + g;
            const int ob = n0 * SC_STRIDE + k0 + 2 * t;
            b_h[ni][0] = *(const uint32_t*)(Bh + ob);
            b_h[ni][1] = *(const uint32_t*)(Bh + ob + 8);
            b_l[ni][0] = *(const uint32_t*)(Bl + ob);
            b_l[ni][1] = *(const uint32_t*)(Bl + ob + 8);
        }
#pragma unroll
        for (int mi = 0; mi < 2; mi++)
#pragma unroll
            for (int ni = 0; ni < 4; ni++) {
                mma_bf16(acc[mi][ni], a_l[mi], b_h[ni]);
                mma_bf16(acc[mi][ni], a_h[mi], b_l[ni]);
                mma_bf16(acc[mi][ni], a_h[mi], b_h[ni]);
            }
    }

    float rsum[2][2] = {{0.f, 0.f}, {0.f, 0.f}};
#pragma unroll
    for (int mi = 0; mi < 2; mi++) {
#pragma unroll
        for (int ni = 0; ni < 4; ni++) {
#pragma unroll
            for (int r = 0; r < 4; r++) {
                float e = __expf(0.125f * acc[mi][ni][r]);
                acc[mi][ni][r] = __uint_as_float(f2tf32(e));   // tf32-representable
            }
            rsum[mi][0] += acc[mi][ni][0] + acc[mi][ni][1];
            rsum[mi][1] += acc[mi][ni][2] + acc[mi][ni][3];

            const long long row0 = bm + wm0 + mi * 16 + g;
            const long long col0 = bn + wn0 + ni * 8 + t * 2;
            float2 v0 = {acc[mi][ni][0], acc[mi][ni][1]};
            float2 v1 = {acc[mi][ni][2], acc[mi][ni][3]};
            *(float2*)(C + row0 * S_LEN + col0) = v0;
            *(float2*)(C + (row0 + 8) * S_LEN + col0) = v1;
        }
    }
#pragma unroll
    for (int mi = 0; mi < 2; mi++)
#pragma unroll
        for (int s = 0; s < 2; s++) {
            float v = rsum[mi][s];
            v += __shfl_xor_sync(0xffffffffu, v, 1);
            v += __shfl_xor_sync(0xffffffffu, v, 2);
            if (t == 0) rowpart[wc][wm0 + mi * 16 + s * 8 + g] = v;
        }
    __syncthreads();
    if (tid < BM) {
        float p = rowpart[0][tid] + rowpart[1][tid];
        part[((long long)z * S_LEN + bm + tid) * NCHUNK + blockIdx.x] = p;
    }
}

// =================================================================
// PV kernel: zero-ALU tf32 mainloop (pre-rounded inputs).
// Normalizes attn in place with float4 stores; out = (e@V)/s,
// output rounded to tf32-representable (for zero-ALU fc).
// 3 CTAs/SM for memory-level parallelism.
// =================================================================
__global__ __launch_bounds__(256, 3) void pv_kernel(
    float* __restrict__ attn, const float* __restrict__ vp,
    float* __restrict__ ao, const float* __restrict__ part)
{
    constexpr int BM = 128, BN = 64, BK = 32;
    constexpr int A_WORDS = BM * (BK + 4);
    constexpr int B_WORDS = BK * (BN + 4);
    constexpr int STAGE_WORDS = A_WORDS + B_WORDS;

    extern __shared__ float smemf[];
    __shared__ float sInv[BM];

    const int z = blockIdx.z;
    const int b = z >> 4, h = z & 15;
    float* A = attn + (long long)z * S_LEN * S_LEN;
    const float* B = vp + (long long)b * S_LEN * DMODEL + h * DHEAD;
    float* C = ao + (long long)b * S_LEN * DMODEL + h * DHEAD;

    const int tid  = threadIdx.x;
    const int warp = tid >> 5;
    const int lane = tid & 31;
    const int g = lane >> 2;
    const int t = lane & 3;
    const int wm0 = (warp >> 1) * 32;
    const int wn0 = (warp & 1) * 32;
    const int bm = blockIdx.y * BM;

    if (tid < BM) {
        const float* p = part + ((long long)z * S_LEN + bm + tid) * NCHUNK;
        float s = 0.0f;
#pragma unroll
        for (int j = 0; j < NCHUNK; j++) s += p[j];
        sInv[tid] = 1.0f / s;
    }

    float acc[2][4][4];
#pragma unroll
    for (int i = 0; i < 2; i++)
#pragma unroll
        for (int j = 0; j < 4; j++)
#pragma unroll
            for (int r = 0; r < 4; r++) acc[i][j][r] = 0.0f;

    auto load_tile = [&](int it, int stage) {
        float* As = smemf + stage * STAGE_WORDS;
        float* Bs = As + A_WORDS;
        const int k0 = it * BK;
#pragma unroll
        for (int i = tid; i < BM * BK / 4; i += 256) {
            int r = i / 8, c = (i % 8) * 4;
            uint32_t dst = (uint32_t)__cvta_generic_to_shared(As + r * (BK + 4) + c);
            cp_async16(dst, A + (long long)(bm + r) * S_LEN + k0 + c);
        }
#pragma unroll
        for (int i = tid; i < BK * BN / 4; i += 256) {
            int r = i / 16, c = (i % 16) * 4;
            uint32_t dst = (uint32_t)__cvta_generic_to_shared(Bs + r * (BN + 4) + c);
            cp_async16(dst, B + (long long)(k0 + r) * DMODEL + c);
        }
    };

    load_tile(0, 0);
    cp_commit();

    const int nIter = S_LEN / BK;   // 64
    for (int it = 0; it < nIter; it++) {
        if (it + 1 < nIter) {
            load_tile(it + 1, (it + 1) & 1);
            cp_commit();
            cp_wait<1>();
        } else {
            cp_wait<0>();
        }
        __syncthreads();

        const float* As = smemf + (it & 1) * STAGE_WORDS;
        const float* Bs = As + A_WORDS;

        // write normalized attn for this tile: float4 stores
#pragma unroll
        for (int i = tid; i < BM * BK / 4; i += 256) {
            const int r = i >> 3, c = (i & 7) * 4;
            const float si = sInv[r];
            float4 vv;
            vv.x = As[r * (BK + 4) + c    ] * si;
            vv.y = As[r * (BK + 4) + c + 1] * si;
            vv.z = As[r * (BK + 4) + c + 2] * si;
            vv.w = As[r * (BK + 4) + c + 3] * si;
            *(float4*)(A + (long long)(bm + r) * S_LEN + it * BK + c) = vv;
        }

#pragma unroll
        for (int ks = 0; ks < BK / 8; ks++) {
            uint32_t ah[2][4], bh[4][2];
#pragma unroll
            for (int mi = 0; mi < 2; mi++) {
                const int r0 = wm0 + mi * 16 + g;
                const int c0 = ks * 8 + t;
                // values already tf32-representable: pass bits directly
                ah[mi][0] = __float_as_uint(As[(r0    ) * (BK + 4) + c0    ]);
                ah[mi][1] = __float_as_uint(As[(r0 + 8) * (BK + 4) + c0    ]);
                ah[mi][2] = __float_as_uint(As[(r0    ) * (BK + 4) + c0 + 4]);
                ah[mi][3] = __float_as_uint(As[(r0 + 8) * (BK + 4) + c0 + 4]);
            }
#pragma unroll
            for (int ni = 0; ni < 4; ni++) {
                const int n0 = wn0 + ni * 8 + g;
                bh[ni][0] = __float_as_uint(Bs[(ks * 8 + t    ) * (BN + 4) + n0]);
                bh[ni][1] = __float_as_uint(Bs[(ks * 8 + t + 4) * (BN + 4) + n0]);
            }
#pragma unroll
            for (int mi = 0; mi < 2; mi++)
#pragma unroll
                for (int ni = 0; ni < 4; ni++)
                    mma_tf32(acc[mi][ni], ah[mi], bh[ni]);
        }
        __syncthreads();
    }

#pragma unroll
    for (int mi = 0; mi < 2; mi++) {
#pragma unroll
        for (int ni = 0; ni < 4; ni++) {
            const int rl0 = wm0 + mi * 16 + g;
            const long long row0 = bm + rl0;
            const long long col0 = wn0 + ni * 8 + t * 2;
            float2 v0, v1;
            v0.x = __uint_as_float(f2tf32(acc[mi][ni][0] * sInv[rl0]));
            v0.y = __uint_as_float(f2tf32(acc[mi][ni][1] * sInv[rl0]));
            v1.x = __uint_as_float(f2tf32(acc[mi][ni][2] * sInv[rl0 + 8]));
            v1.y = __uint_as_float(f2tf32(acc[mi][ni][3] * sInv[rl0 + 8]));
            *(float2*)(C + row0 * DMODEL + col0) = v0;
            *(float2*)(C + (row0 + 8) * DMODEL + col0) = v1;
        }
    }
}

// =================================================================
// In-place LayerNorm over rows of length DMODEL (1024). 256 threads.
// =================================================================
__global__ __launch_bounds__(256) void ln_kernel(float* __restrict__ x,
                                                 const float* __restrict__ gamma,
                                                 const float* __restrict__ beta)
{
    float* row = x + (size_t)blockIdx.x * DMODEL;
    const int tid = threadIdx.x;
    __shared__ float ssum[8], ssq[8];

    float v[4];
    float s = 0.0f, sq = 0.0f;
#pragma unroll
    for (int j = 0; j < 4; j++) {
        v[j] = row[tid + j * 256];
        s += v[j];
        sq += v[j] * v[j];
    }
#pragma unroll
    for (int o = 16; o > 0; o >>= 1) {
        s  += __shfl_xor_sync(0xffffffffu, s, o);
        sq += __shfl_xor_sync(0xffffffffu, sq, o);
    }
    if ((tid & 31) == 0) { ssum[tid >> 5] = s; ssq[tid >> 5] = sq; }
    __syncthreads();
    s = 0.0f; sq = 0.0f;
#pragma unroll
    for (int j = 0; j < 8; j++) { s += ssum[j]; sq += ssq[j]; }

    const float mu = s * (1.0f / DMODEL);
    const float var = sq * (1.0f / DMODEL) - mu * mu;
    const float rstd = rsqrtf(var + 1e-6f);
#pragma unroll
    for (int j = 0; j < 4; j++) {
        const int c = tid + j * 256;
        row[c] = (v[j] - mu) * rstd * gamma[c] + beta[c];
    }
}

// =================================================================
static constexpr int GEMM_SMEM = 2 * (128 * 36 + 64 * 36) * 4;         // 55296 B
static constexpr int PROJ_SMEM = 2 * (2 * 128 * 40 + 2 * 64 * 40) * 2; // 61440 B
static constexpr int SC_SMEM   = (2 * 128 * 72 + 2 * 64 * 72) * 2;     // 55296 B
static constexpr int PV_SMEM   = 2 * (128 * 36 + 32 * 68) * 4;         // 54272 B

extern "C" void kernel_launch(void* const* d_in, const int* in_sizes, int n_in,
                              void* d_out, int out_size)
{
    const float* q     = (const float*)d_in[0];
    const float* k     = (const float*)d_in[1];
    const float* v     = (const float*)d_in[2];
    const float* w_q   = (const float*)d_in[3];
    const float* w_k   = (const float*)d_in[4];
    const float* w_v   = (const float*)d_in[5];
    const float* w_fc  = (const float*)d_in[6];
    const float* gamma = (const float*)d_in[7];
    const float* beta  = (const float*)d_in[8];

    __nv_bfloat16 *qs, *ks_, *q2, *k2, *wq2, *wk2;
    float *vp, *ao, *wfr, *part;
    cudaGetSymbolAddress((void**)&qs, g_qs);
    cudaGetSymbolAddress((void**)&ks_, g_ks);
    cudaGetSymbolAddress((void**)&q2, g_q2);
    cudaGetSymbolAddress((void**)&k2, g_k2);
    cudaGetSymbolAddress((void**)&wq2, g_wq2);
    cudaGetSymbolAddress((void**)&wk2, g_wk2);
    cudaGetSymbolAddress((void**)&vp, g_vp);
    cudaGetSymbolAddress((void**)&ao, g_ao);
    cudaGetSymbolAddress((void**)&wfr, g_wf);
    cudaGetSymbolAddress((void**)&part, g_part);

    float* out  = (float*)d_out;
    float* attn = out + (size_t)MROWS * DMODEL;   // [B, H, Sq, Sk] fp32

    cudaFuncSetAttribute(proj_bf16_kernel,
                         cudaFuncAttributeMaxDynamicSharedMemorySize, PROJ_SMEM);
    cudaFuncSetAttribute(gemm_tc<true,false,true,false>,
                         cudaFuncAttributeMaxDynamicSharedMemorySize, GEMM_SMEM);
    cudaFuncSetAttribute(gemm_tc<true,true,false,true>,
                         cudaFuncAttributeMaxDynamicSharedMemorySize, GEMM_SMEM);
    cudaFuncSetAttribute(scores_kernel,
                         cudaFuncAttributeMaxDynamicSharedMemorySize, SC_SMEM);
    cudaFuncSetAttribute(pv_kernel,
                         cudaFuncAttributeMaxDynamicSharedMemorySize, PV_SMEM);

    dim3 blk(256);
    const int actBlocks = MROWS * (DMODEL / 4) / 256;   // 8192
    const int wBlocks   = DMODEL * (DMODEL / 4) / 256;  // 1024

    // --- split q, k, w_q, w_k into bf16 hi|lo planes; round w_fc ---
    split_planes<<<actBlocks, blk>>>(q, q2, MROWS);
    split_planes<<<actBlocks, blk>>>(k, k2, MROWS);
    split_planes<<<wBlocks, blk>>>(w_q, wq2, DMODEL);
    split_planes<<<wBlocks, blk>>>(w_k, wk2, DMODEL);
    round_tf32_kernel<<<wBlocks, blk>>>(w_fc, wfr, DMODEL * DMODEL / 4);

    // --- Q/K projections: zero-ALU bf16x3 GEMM from planes ---
    {
        dim3 g(DMODEL / 64, MROWS / 128, 1);
        proj_bf16_kernel<<<g, blk, PROJ_SMEM>>>(q2, wq2, qs);
        proj_bf16_kernel<<<g, blk, PROJ_SMEM>>>(k2, wk2, ks_);
    }
    // --- V projection (single tf32, output rounded to tf32) ---
    {
        dim3 g(DMODEL / 64, MROWS / 128, 1);
        gemm_tc<true,false,true,false><<<g, blk, GEMM_SMEM>>>(
            v, DMODEL, w_v, DMODEL, vp, DMODEL, DMODEL, 1.0f, nullptr);
    }

    // --- scores (bf16x3) + exp (tf32-rounded) + partials ---
    {
        dim3 g(S_LEN / 64, S_LEN / 128, NZ);
        scores_kernel<<<g, blk, SC_SMEM>>>(qs, ks_, attn, part);
    }

    // --- PV (zero-ALU tf32, 3 CTAs/SM) + in-place normalization ---
    {
        dim3 g(1, S_LEN / 128, NZ);
        pv_kernel<<<g, blk, PV_SMEM>>>(attn, vp, ao, part);
    }

    // --- fc + residual (zero-ALU tf32: pre-rounded ao and w_fc) ---
    {
        dim3 g(DMODEL / 64, MROWS / 128, 1);
        gemm_tc<true,true,false,true><<<g, blk, GEMM_SMEM>>>(
            ao, DMODEL, wfr, DMODEL, out, DMODEL, DMODEL, 1.0f, q);
    }

    // --- layernorm in place ---
    ln_kernel<<<MROWS, blk>>>(out, gamma, beta);
}

// round 14
// speedup vs baseline: 1.0838x; 1.0027x over previous
#include <cuda_runtime.h>
#include <cuda_bf16.h>
#include <math.h>
#include <stdint.h>

#define S_LEN  2048
#define BATCH  4
#define NHEAD  16
#define DMODEL 1024
#define DHEAD  64
#define MROWS  (BATCH * S_LEN)   // 8192
#define NZ     (BATCH * NHEAD)   // 64
#define NCHUNK 32                // scores grid.x chunks
#define LDHL   (NHEAD * 128)     // 2048 bf16 per row: per head hi(64)|lo(64)
#define LD2    (2 * DMODEL)      // 2048: hi|lo plane row stride

// ---------------- scratch (no allocations allowed) ----------------
__device__ __nv_bfloat16 g_qs[(size_t)MROWS * LDHL];  // per-head compact q hi|lo
__device__ __nv_bfloat16 g_ks[(size_t)MROWS * LDHL];  // per-head compact k hi|lo
__device__ __nv_bfloat16 g_q2[(size_t)MROWS * LD2];   // q input planes [row][hi|lo]
__device__ __nv_bfloat16 g_k2[(size_t)MROWS * LD2];   // k input planes
__device__ __nv_bfloat16 g_wq2[(size_t)DMODEL * LD2]; // w_q planes [out][hi|lo]
__device__ __nv_bfloat16 g_wk2[(size_t)DMODEL * LD2]; // w_k planes
__device__ float g_vp[(size_t)MROWS * DMODEL];        // tf32-rounded V proj
__device__ float g_ao[(size_t)MROWS * DMODEL];        // tf32-rounded PV out
__device__ float g_wf[(size_t)DMODEL * DMODEL];       // tf32-rounded w_fc
__device__ float g_part[(size_t)NZ * S_LEN * NCHUNK];

// ---------------- helpers ----------------
__device__ __forceinline__ void mma_tf32(float c[4], const uint32_t a[4], const uint32_t b[2]) {
    asm volatile(
        "mma.sync.aligned.m16n8k8.row.col.f32.tf32.tf32.f32 "
        "{%0,%1,%2,%3}, {%4,%5,%6,%7}, {%8,%9}, {%0,%1,%2,%3};\n"
        : "+f"(c[0]), "+f"(c[1]), "+f"(c[2]), "+f"(c[3])
        : "r"(a[0]), "r"(a[1]), "r"(a[2]), "r"(a[3]), "r"(b[0]), "r"(b[1]));
}
__device__ __forceinline__ void mma_bf16(float c[4], const uint32_t a[4], const uint32_t b[2]) {
    asm volatile(
        "mma.sync.aligned.m16n8k16.row.col.f32.bf16.bf16.f32 "
        "{%0,%1,%2,%3}, {%4,%5,%6,%7}, {%8,%9}, {%0,%1,%2,%3};\n"
        : "+f"(c[0]), "+f"(c[1]), "+f"(c[2]), "+f"(c[3])
        : "r"(a[0]), "r"(a[1]), "r"(a[2]), "r"(a[3]), "r"(b[0]), "r"(b[1]));
}
__device__ __forceinline__ uint32_t f2tf32(float x) {
    uint32_t r;
    asm("cvt.rna.tf32.f32 %0, %1;\n" : "=r"(r) : "f"(x));
    return r;
}
__device__ __forceinline__ void cp_async16(uint32_t smem_addr, const void* gptr) {
    asm volatile("cp.async.cg.shared.global [%0], [%1], 16;\n" :: "r"(smem_addr), "l"(gptr));
}
__device__ __forceinline__ void cp_commit() { asm volatile("cp.async.commit_group;\n"); }
template <int N> __device__ __forceinline__ void cp_wait() {
    asm volatile("cp.async.wait_group %0;\n" :: "n"(N));
}

// =================================================================
// Split fp32 -> bf16 hi|lo planes.
// =================================================================
__global__ __launch_bounds__(256) void split_planes(
    const float* __restrict__ x, __nv_bfloat16* __restrict__ o, int rows)
{
    const int n4 = rows * (DMODEL / 4);
    int idx = blockIdx.x * 256 + threadIdx.x;
    if (idx >= n4) return;
    const int row = idx / (DMODEL / 4);
    const int c4  = idx % (DMODEL / 4);
    const float4 v = ((const float4*)x)[idx];
    __nv_bfloat16 h[4], l[4];
    h[0] = __float2bfloat16(v.x); l[0] = __float2bfloat16(v.x - __bfloat162float(h[0]));
    h[1] = __float2bfloat16(v.y); l[1] = __float2bfloat16(v.y - __bfloat162float(h[1]));
    h[2] = __float2bfloat16(v.z); l[2] = __float2bfloat16(v.z - __bfloat162float(h[2]));
    h[3] = __float2bfloat16(v.w); l[3] = __float2bfloat16(v.w - __bfloat162float(h[3]));
    *(uint2*)(o + (size_t)row * LD2 + c4 * 4)          = *(const uint2*)h;
    *(uint2*)(o + (size_t)row * LD2 + DMODEL + c4 * 4) = *(const uint2*)l;
}

// =================================================================
// Round fp32 array to tf32-representable fp32 (for zero-ALU GEMMs).
// =================================================================
__global__ __launch_bounds__(256) void round_tf32_kernel(
    const float* __restrict__ x, float* __restrict__ o, int n4)
{
    int idx = blockIdx.x * 256 + threadIdx.x;
    if (idx >= n4) return;
    float4 v = ((const float4*)x)[idx];
    v.x = __uint_as_float(f2tf32(v.x));
    v.y = __uint_as_float(f2tf32(v.y));
    v.z = __uint_as_float(f2tf32(v.z));
    v.w = __uint_as_float(f2tf32(v.w));
    ((float4*)o)[idx] = v;
}

// =================================================================
// Q/K projection: zero-ALU bf16x3 GEMM over precomputed planes.
// Epilogue writes compact per-head bf16 hi|lo layout.
// =================================================================
#define PS 40   // bf16 smem row stride (32 + 8 pad)

__global__ __launch_bounds__(256, 2) void proj_bf16_kernel(
    const __nv_bfloat16* __restrict__ A2,
    const __nv_bfloat16* __restrict__ B2,
    __nv_bfloat16* __restrict__ C)
{
    constexpr int BM = 128, BN = 64, BK = 32;
    constexpr int APL = BM * PS;
    constexpr int BPL = BN * PS;
    constexpr int STAGE = 2 * APL + 2 * BPL;

    extern __shared__ __nv_bfloat16 smemb[];

    const int tid  = threadIdx.x;
    const int warp = tid >> 5;
    const int lane = tid & 31;
    const int g = lane >> 2;
    const int t = lane & 3;
    const int wm0 = (warp >> 1) * 32;
    const int wn0 = (warp & 1) * 32;
    const int bm = blockIdx.y * BM, bn = blockIdx.x * BN;

    float acc[2][4][4];
#pragma unroll
    for (int i = 0; i < 2; i++)
#pragma unroll
        for (int j = 0; j < 4; j++)
#pragma unroll
            for (int r = 0; r < 4; r++) acc[i][j][r] = 0.0f;

    auto load_tile = [&](int it, int stage) {
        __nv_bfloat16* Ah = smemb + stage * STAGE;
        __nv_bfloat16* Al = Ah + APL;
        __nv_bfloat16* Bh = Al + APL;
        __nv_bfloat16* Bl = Bh + BPL;
        const int k0 = it * BK;
#pragma unroll
        for (int i = tid; i < BM * 4; i += 256) {
            const int r = i >> 2, c = (i & 3) * 8;
            const __nv_bfloat16* src = A2 + (size_t)(bm + r) * LD2 + k0 + c;
            cp_async16((uint32_t)__cvta_generic_to_shared(Ah + r * PS + c), src);
            cp_async16((uint32_t)__cvta_generic_to_shared(Al + r * PS + c), src + DMODEL);
        }
#pragma unroll
        for (int i = tid; i < BN * 4; i += 256) {
            const int r = i >> 2, c = (i & 3) * 8;
            const __nv_bfloat16* src = B2 + (size_t)(bn + r) * LD2 + k0 + c;
            cp_async16((uint32_t)__cvta_generic_to_shared(Bh + r * PS + c), src);
            cp_async16((uint32_t)__cvta_generic_to_shared(Bl + r * PS + c), src + DMODEL);
        }
    };

    load_tile(0, 0);
    cp_commit();

    constexpr int nIter = DMODEL / BK;   // 32
    for (int it = 0; it < nIter; it++) {
        if (it + 1 < nIter) {
            load_tile(it + 1, (it + 1) & 1);
            cp_commit();
            cp_wait<1>();
        } else {
            cp_wait<0>();
        }
        __syncthreads();

        const __nv_bfloat16* Ah = smemb + (it & 1) * STAGE;
        const __nv_bfloat16* Al = Ah + APL;
        const __nv_bfloat16* Bh = Al + APL;
        const __nv_bfloat16* Bl = Bh + BPL;

#pragma unroll
        for (int ks = 0; ks < 2; ks++) {
            const int k0 = ks * 16;
            uint32_t a_h[2][4], a_l[2][4], b_h[4][2], b_l[4][2];
#pragma unroll
            for (int mi = 0; mi < 2; mi++) {
                const int r0 = wm0 + mi * 16 + g;
                const int o0 = r0 * PS + k0 + 2 * t;
                const int o1 = (r0 + 8) * PS + k0 + 2 * t;
                a_h[mi][0] = *(const uint32_t*)(Ah + o0);
                a_h[mi][1] = *(const uint32_t*)(Ah + o1);
                a_h[mi][2] = *(const uint32_t*)(Ah + o0 + 8);
                a_h[mi][3] = *(const uint32_t*)(Ah + o1 + 8);
                a_l[mi][0] = *(const uint32_t*)(Al + o0);
                a_l[mi][1] = *(const uint32_t*)(Al + o1);
                a_l[mi][2] = *(const uint32_t*)(Al + o0 + 8);
                a_l[mi][3] = *(const uint32_t*)(Al + o1 + 8);
            }
#pragma unroll
            for (int ni = 0; ni < 4; ni++) {
                const int n0 = wn0 + ni * 8 + g;
                const int ob = n0 * PS + k0 + 2 * t;
                b_h[ni][0] = *(const uint32_t*)(Bh + ob);
                b_h[ni][1] = *(const uint32_t*)(Bh + ob + 8);
                b_l[ni][0] = *(const uint32_t*)(Bl + ob);
                b_l[ni][1] = *(const uint32_t*)(Bl + ob + 8);
            }
#pragma unroll
            for (int mi = 0; mi < 2; mi++)
#pragma unroll
                for (int ni = 0; ni < 4; ni++) {
                    mma_bf16(acc[mi][ni], a_l[mi], b_h[ni]);
                    mma_bf16(acc[mi][ni], a_h[mi], b_l[ni]);
                    mma_bf16(acc[mi][ni], a_h[mi], b_h[ni]);
                }
        }
        __syncthreads();
    }

    // ---- epilogue: compact per-head bf16 hi|lo ----
#pragma unroll
    for (int mi = 0; mi < 2; mi++) {
#pragma unroll
        for (int ni = 0; ni < 4; ni++) {
            const long long row0 = bm + wm0 + mi * 16 + g;
            const long long col0 = bn + wn0 + ni * 8 + t * 2;
#pragma unroll
            for (int e = 0; e < 4; e++) {
                const long long row = row0 + (e >> 1) * 8;
                const int col = (int)col0 + (e & 1);
                const float val = acc[mi][ni][e];
                const __nv_bfloat16 hi = __float2bfloat16(val);
                const __nv_bfloat16 lo = __float2bfloat16(val - __bfloat162float(hi));
                const long long base = row * LDHL + (col >> 6) * 128 + (col & 63);
                C[base     ] = hi;
                C[base + 64] = lo;
            }
        }
    }
}

// =================================================================
// Generic tensor-core tf32 GEMM (V proj, fc). BM=128, BN=64, BK=32.
// RND: epilogue rounds output to tf32-representable fp32.
// PT:  inputs already tf32-representable -> zero-ALU (bit pass).
// =================================================================
template <bool TRANSB, bool RES, bool RND, bool PT>
__global__ __launch_bounds__(256, 2) void gemm_tc(
    const float* __restrict__ A, int lda,
    const float* __restrict__ B, int ldb,
    float* __restrict__ C, int ldc,
    int K, float alpha, const float* __restrict__ Res)
{
    constexpr int BM = 128, BN = 64, BK = 32;
    constexpr int MI = 2, NI = 4;
    constexpr int A_WORDS = BM * (BK + 4);
    constexpr int B_WORDS = TRANSB ? BN * (BK + 4) : BK * (BN + 4);
    constexpr int STAGE_WORDS = A_WORDS + B_WORDS;

    extern __shared__ float smemf[];

    const int tid  = threadIdx.x;
    const int warp = tid >> 5;
    const int lane = tid & 31;
    const int g = lane >> 2;
    const int t = lane & 3;
    const int wm0 = (warp >> 1) * 32;
    const int wn0 = (warp & 1) * 32;
    const int bm = blockIdx.y * BM, bn = blockIdx.x * BN;

    float acc[MI][NI][4];
#pragma unroll
    for (int i = 0; i < MI; i++)
#pragma unroll
        for (int j = 0; j < NI; j++)
#pragma unroll
            for (int r = 0; r < 4; r++) acc[i][j][r] = 0.0f;

    const int nIter = K / BK;

    auto load_tile = [&](int it, int stage) {
        float* As = smemf + stage * STAGE_WORDS;
        float* Bs = As + A_WORDS;
        const int k0 = it * BK;
#pragma unroll
        for (int i = tid; i < BM * BK / 4; i += 256) {
            int r = i / 8, c = (i % 8) * 4;
            uint32_t dst = (uint32_t)__cvta_generic_to_shared(As + r * (BK + 4) + c);
            cp_async16(dst, A + (long long)(bm + r) * lda + k0 + c);
        }
        if (TRANSB) {
#pragma unroll
            for (int i = tid; i < BN * BK / 4; i += 256) {
                int r = i / 8, c = (i % 8) * 4;
                uint32_t dst = (uint32_t)__cvta_generic_to_shared(Bs + r * (BK + 4) + c);
                cp_async16(dst, B + (long long)(bn + r) * ldb + k0 + c);
            }
        } else {
#pragma unroll
            for (int i = tid; i < BK * BN / 4; i += 256) {
                int r = i / 16, c = (i % 16) * 4;
                uint32_t dst = (uint32_t)__cvta_generic_to_shared(Bs + r * (BN + 4) + c);
                cp_async16(dst, B + (long long)(k0 + r) * ldb + bn + c);
            }
        }
    };

    load_tile(0, 0);
    cp_commit();

    for (int it = 0; it < nIter; it++) {
        if (it + 1 < nIter) {
            load_tile(it + 1, (it + 1) & 1);
            cp_commit();
            cp_wait<1>();
        } else {
            cp_wait<0>();
        }
        __syncthreads();

        const float* As = smemf + (it & 1) * STAGE_WORDS;
        const float* Bs = As + A_WORDS;

#pragma unroll
        for (int ks = 0; ks < BK / 8; ks++) {
            uint32_t ah[MI][4], bh[NI][2];
#pragma unroll
            for (int mi = 0; mi < MI; mi++) {
                const int r0 = wm0 + mi * 16 + g;
                const int c0 = ks * 8 + t;
                if (PT) {
                    ah[mi][0] = __float_as_uint(As[(r0    ) * (BK + 4) + c0    ]);
                    ah[mi][1] = __float_as_uint(As[(r0 + 8) * (BK + 4) + c0    ]);
                    ah[mi][2] = __float_as_uint(As[(r0    ) * (BK + 4) + c0 + 4]);
                    ah[mi][3] = __float_as_uint(As[(r0 + 8) * (BK + 4) + c0 + 4]);
                } else {
                    ah[mi][0] = f2tf32(As[(r0    ) * (BK + 4) + c0    ]);
                    ah[mi][1] = f2tf32(As[(r0 + 8) * (BK + 4) + c0    ]);
                    ah[mi][2] = f2tf32(As[(r0    ) * (BK + 4) + c0 + 4]);
                    ah[mi][3] = f2tf32(As[(r0 + 8) * (BK + 4) + c0 + 4]);
                }
            }
#pragma unroll
            for (int ni = 0; ni < NI; ni++) {
                const int n0 = wn0 + ni * 8 + g;
                float b0, b1;
                if (TRANSB) {
                    b0 = Bs[n0 * (BK + 4) + ks * 8 + t    ];
                    b1 = Bs[n0 * (BK + 4) + ks * 8 + t + 4];
                } else {
                    b0 = Bs[(ks * 8 + t    ) * (BN + 4) + n0];
                    b1 = Bs[(ks * 8 + t + 4) * (BN + 4) + n0];
                }
                if (PT) {
                    bh[ni][0] = __float_as_uint(b0);
                    bh[ni][1] = __float_as_uint(b1);
                } else {
                    bh[ni][0] = f2tf32(b0);
                    bh[ni][1] = f2tf32(b1);
                }
            }
#pragma unroll
            for (int mi = 0; mi < MI; mi++)
#pragma unroll
                for (int ni = 0; ni < NI; ni++)
                    mma_tf32(acc[mi][ni], ah[mi], bh[ni]);
        }
        __syncthreads();
    }

#pragma unroll
    for (int mi = 0; mi < MI; mi++) {
#pragma unroll
        for (int ni = 0; ni < NI; ni++) {
            const long long row0 = bm + wm0 + mi * 16 + g;
            const long long col0 = bn + wn0 + ni * 8 + t * 2;
            float2 v0, v1;
            v0.x = alpha * acc[mi][ni][0];
            v0.y = alpha * acc[mi][ni][1];
            v1.x = alpha * acc[mi][ni][2];
            v1.y = alpha * acc[mi][ni][3];
            if (RES) {
                const float2 r0 = *(const float2*)(Res + row0 * ldc + col0);
                const float2 r1 = *(const float2*)(Res + (row0 + 8) * ldc + col0);
                v0.x += r0.x; v0.y += r0.y;
                v1.x += r1.x; v1.y += r1.y;
            }
            if (RND) {
                v0.x = __uint_as_float(f2tf32(v0.x));
                v0.y = __uint_as_float(f2tf32(v0.y));
                v1.x = __uint_as_float(f2tf32(v1.x));
                v1.y = __uint_as_float(f2tf32(v1.y));
            }
            *(float2*)(C + row0 * ldc + col0) = v0;
            *(float2*)(C + (row0 + 8) * ldc + col0) = v1;
        }
    }
}

// =================================================================
// Scores: bf16x3 compensated GEMM from compact hi/lo layout.
// exp values rounded to tf32-representable fp32 before store.
// =================================================================
#define SC_STRIDE 72   // bf16 elements per smem row (64 + 8 pad)

__global__ __launch_bounds__(256, 3) void scores_kernel(
    const __nv_bfloat16* __restrict__ qs, const __nv_bfloat16* __restrict__ ks_,
    float* __restrict__ attn, float* __restrict__ part)
{
    constexpr int BM = 128, BN = 64;
    constexpr int AT = BM * SC_STRIDE;
    constexpr int BT = BN * SC_STRIDE;

    extern __shared__ __nv_bfloat16 smemb[];
    __nv_bfloat16* Ah = smemb;
    __nv_bfloat16* Al = Ah + AT;
    __nv_bfloat16* Bh = Al + AT;
    __nv_bfloat16* Bl = Bh + BT;
    __shared__ float rowpart[2][BM];

    const int z = blockIdx.z;
    const int b = z >> 4, h = z & 15;
    const __nv_bfloat16* Aq = qs + (long long)b * S_LEN * LDHL + h * 128;
    const __nv_bfloat16* Bk = ks_ + (long long)b * S_LEN * LDHL + h * 128;
    float* C = attn + (long long)z * S_LEN * S_LEN;

    const int tid  = threadIdx.x;
    const int warp = tid >> 5;
    const int lane = tid & 31;
    const int g = lane >> 2;
    const int t = lane & 3;
    const int wm0 = (warp >> 1) * 32;
    const int wn0 = (warp & 1) * 32;
    const int wc  = warp & 1;
    const int bm = blockIdx.y * BM, bn = blockIdx.x * BN;

#pragma unroll
    for (int i = tid; i < BM * 8; i += 256) {
        const int r = i >> 3, c = (i & 7) * 8;
        const __nv_bfloat16* src = Aq + (long long)(bm + r) * LDHL + c;
        cp_async16((uint32_t)__cvta_generic_to_shared(Ah + r * SC_STRIDE + c), src);
        cp_async16((uint32_t)__cvta_generic_to_shared(Al + r * SC_STRIDE + c), src + 64);
    }
#pragma unroll
    for (int i = tid; i < BN * 8; i += 256) {
        const int r = i >> 3, c = (i & 7) * 8;
        const __nv_bfloat16* src = Bk + (long long)(bn + r) * LDHL + c;
        cp_async16((uint32_t)__cvta_generic_to_shared(Bh + r * SC_STRIDE + c), src);
        cp_async16((uint32_t)__cvta_generic_to_shared(Bl + r * SC_STRIDE + c), src + 64);
    }
    cp_commit();
    cp_wait<0>();
    __syncthreads();

    float acc[2][4][4];
#pragma unroll
    for (int i = 0; i < 2; i++)
#pragma unroll
        for (int j = 0; j < 4; j++)
#pragma unroll
            for (int r = 0; r < 4; r++) acc[i][j][r] = 0.0f;

#pragma unroll
    for (int ks = 0; ks < 4; ks++) {
        const int k0 = ks * 16;
        uint32_t a_h[2][4], a_l[2][4], b_h[4][2], b_l[4][2];
#pragma unroll
        for (int mi = 0; mi < 2; mi++) {
            const int r0 = wm0 + mi * 16 + g;
            const int o0 = r0 * SC_STRIDE + k0 + 2 * t;
            const int o1 = (r0 + 8) * SC_STRIDE + k0 + 2 * t;
            a_h[mi][0] = *(const uint32_t*)(Ah + o0);
            a_h[mi][1] = *(const uint32_t*)(Ah + o1);
            a_h[mi][2] = *(const uint32_t*)(Ah + o0 + 8);
            a_h[mi][3] = *(const uint32_t*)(Ah + o1 + 8);
            a_l[mi][0] = *(const uint32_t*)(Al + o0);
            a_l[mi][1] = *(const uint32_t*)(Al + o1);
            a_l[mi][2] = *(const uint32_t*)(Al + o0 + 8);
            a_l[mi][3] = *(const uint32_t*)(Al + o1 + 8);
        }
#pragma unroll
        for (int ni = 0; ni < 4; ni++) {
            const int n0 = wn0 + ni * 8 + g;
            const int ob = n0 * SC_STRIDE + k0 + 2 * t;
            b_h[ni][0] = *(const uint32_t*)(Bh + ob);
            b_h[ni][1] = *(const uint32_t*)(Bh + ob + 8);
            b_l[ni][0] = *(const uint32_t*)(Bl + ob);
            b_l[ni][1] = *(const uint32_t*)(Bl + ob + 8);
        }
#pragma unroll
        for (int mi = 0; mi < 2; mi++)
#pragma unroll
            for (int ni = 0; ni < 4; ni++) {
                mma_bf16(acc[mi][ni], a_l[mi], b_h[ni]);
                mma_bf16(acc[mi][ni], a_h[mi], b_l[ni]);
                mma_bf16(acc[mi][ni], a_h[mi], b_h[ni]);
            }
    }

    float rsum[2][2] = {{0.f, 0.f}, {0.f, 0.f}};
#pragma unroll
    for (int mi = 0; mi < 2; mi++) {
#pragma unroll
        for (int ni = 0; ni < 4; ni++) {
#pragma unroll
            for (int r = 0; r < 4; r++) {
                float e = __expf(0.125f * acc[mi][ni][r]);
                acc[mi][ni][r] = __uint_as_float(f2tf32(e));   // tf32-representable
            }
            rsum[mi][0] += acc[mi][ni][0] + acc[mi][ni][1];
            rsum[mi][1] += acc[mi][ni][2] + acc[mi][ni][3];

            const long long row0 = bm + wm0 + mi * 16 + g;
            const long long col0 = bn + wn0 + ni * 8 + t * 2;
            float2 v0 = {acc[mi][ni][0], acc[mi][ni][1]};
            float2 v1 = {acc[mi][ni][2], acc[mi][ni][3]};
            *(float2*)(C + row0 * S_LEN + col0) = v0;
            *(float2*)(C + (row0 + 8) * S_LEN + col0) = v1;
        }
    }
#pragma unroll
    for (int mi = 0; mi < 2; mi++)
#pragma unroll
        for (int s = 0; s < 2; s++) {
            float v = rsum[mi][s];
            v += __shfl_xor_sync(0xffffffffu, v, 1);
            v += __shfl_xor_sync(0xffffffffu, v, 2);
            if (t == 0) rowpart[wc][wm0 + mi * 16 + s * 8 + g] = v;
        }
    __syncthreads();
    if (tid < BM) {
        float p = rowpart[0][tid] + rowpart[1][tid];
        part[((long long)z * S_LEN + bm + tid) * NCHUNK + blockIdx.x] = p;
    }
}

// =================================================================
// PV kernel: zero-ALU tf32 mainloop, 4-stage cp.async pipeline
// (3 tiles in flight) to cover DRAM latency. Normalizes attn in
// place with float4 stores; out = (e@V)/s (tf32-rounded).
// =================================================================
#define PV_STAGES 4

__global__ __launch_bounds__(256, 2) void pv_kernel(
    float* __restrict__ attn, const float* __restrict__ vp,
    float* __restrict__ ao, const float* __restrict__ part)
{
    constexpr int BM = 128, BN = 64, BK = 32;
    constexpr int A_WORDS = BM * (BK + 4);
    constexpr int B_WORDS = BK * (BN + 4);
    constexpr int STAGE_WORDS = A_WORDS + B_WORDS;   // 6784

    extern __shared__ float smemf[];
    __shared__ float sInv[BM];

    const int z = blockIdx.z;
    const int b = z >> 4, h = z & 15;
    float* A = attn + (long long)z * S_LEN * S_LEN;
    const float* B = vp + (long long)b * S_LEN * DMODEL + h * DHEAD;
    float* C = ao + (long long)b * S_LEN * DMODEL + h * DHEAD;

    const int tid  = threadIdx.x;
    const int warp = tid >> 5;
    const int lane = tid & 31;
    const int g = lane >> 2;
    const int t = lane & 3;
    const int wm0 = (warp >> 1) * 32;
    const int wn0 = (warp & 1) * 32;
    const int bm = blockIdx.y * BM;

    if (tid < BM) {
        const float* p = part + ((long long)z * S_LEN + bm + tid) * NCHUNK;
        float s = 0.0f;
#pragma unroll
        for (int j = 0; j < NCHUNK; j++) s += p[j];
        sInv[tid] = 1.0f / s;
    }

    float acc[2][4][4];
#pragma unroll
    for (int i = 0; i < 2; i++)
#pragma unroll
        for (int j = 0; j < 4; j++)
#pragma unroll
            for (int r = 0; r < 4; r++) acc[i][j][r] = 0.0f;

    auto load_tile = [&](int it, int stage) {
        float* As = smemf + stage * STAGE_WORDS;
        float* Bs = As + A_WORDS;
        const int k0 = it * BK;
#pragma unroll
        for (int i = tid; i < BM * BK / 4; i += 256) {
            int r = i / 8, c = (i % 8) * 4;
            uint32_t dst = (uint32_t)__cvta_generic_to_shared(As + r * (BK + 4) + c);
            cp_async16(dst, A + (long long)(bm + r) * S_LEN + k0 + c);
        }
#pragma unroll
        for (int i = tid; i < BK * BN / 4; i += 256) {
            int r = i / 16, c = (i % 16) * 4;
            uint32_t dst = (uint32_t)__cvta_generic_to_shared(Bs + r * (BN + 4) + c);
            cp_async16(dst, B + (long long)(k0 + r) * DMODEL + c);
        }
    };

    const int nIter = S_LEN / BK;   // 64

    // prologue: preload 3 tiles
#pragma unroll
    for (int it = 0; it < PV_STAGES - 1; it++) {
        load_tile(it, it);
        cp_commit();
    }

    for (int it = 0; it < nIter; it++) {
        cp_wait<PV_STAGES - 2>();   // oldest group (tile it) complete
        __syncthreads();

        const float* As = smemf + (it % PV_STAGES) * STAGE_WORDS;
        const float* Bs = As + A_WORDS;

        // write normalized attn for this tile: float4 stores
#pragma unroll
        for (int i = tid; i < BM * BK / 4; i += 256) {
            const int r = i >> 3, c = (i & 7) * 4;
            const float si = sInv[r];
            float4 vv;
            vv.x = As[r * (BK + 4) + c    ] * si;
            vv.y = As[r * (BK + 4) + c + 1] * si;
            vv.z = As[r * (BK + 4) + c + 2] * si;
            vv.w = As[r * (BK + 4) + c + 3] * si;
            *(float4*)(A + (long long)(bm + r) * S_LEN + it * BK + c) = vv;
        }

#pragma unroll
        for (int ks = 0; ks < BK / 8; ks++) {
            uint32_t ah[2][4], bh[4][2];
#pragma unroll
            for (int mi = 0; mi < 2; mi++) {
                const int r0 = wm0 + mi * 16 + g;
                const int c0 = ks * 8 + t;
                // values already tf32-representable: pass bits directly
                ah[mi][0] = __float_as_uint(As[(r0    ) * (BK + 4) + c0    ]);
                ah[mi][1] = __float_as_uint(As[(r0 + 8) * (BK + 4) + c0    ]);
                ah[mi][2] = __float_as_uint(As[(r0    ) * (BK + 4) + c0 + 4]);
                ah[mi][3] = __float_as_uint(As[(r0 + 8) * (BK + 4) + c0 + 4]);
            }
#pragma unroll
            for (int ni = 0; ni < 4; ni++) {
                const int n0 = wn0 + ni * 8 + g;
                bh[ni][0] = __float_as_uint(Bs[(ks * 8 + t    ) * (BN + 4) + n0]);
                bh[ni][1] = __float_as_uint(Bs[(ks * 8 + t + 4) * (BN + 4) + n0]);
            }
#pragma unroll
            for (int mi = 0; mi < 2; mi++)
#pragma unroll
                for (int ni = 0; ni < 4; ni++)
                    mma_tf32(acc[mi][ni], ah[mi], bh[ni]);
        }
        __syncthreads();

        // issue next load (empty commit in tail keeps wait-count invariant)
        if (it + PV_STAGES - 1 < nIter)
            load_tile(it + PV_STAGES - 1, (it + PV_STAGES - 1) % PV_STAGES);
        cp_commit();
    }

#pragma unroll
    for (int mi = 0; mi < 2; mi++) {
#pragma unroll
        for (int ni = 0; ni < 4; ni++) {
            const int rl0 = wm0 + mi * 16 + g;
            const long long row0 = bm + rl0;
            const long long col0 = wn0 + ni * 8 + t * 2;
            float2 v0, v1;
            v0.x = __uint_as_float(f2tf32(acc[mi][ni][0] * sInv[rl0]));
            v0.y = __uint_as_float(f2tf32(acc[mi][ni][1] * sInv[rl0]));
            v1.x = __uint_as_float(f2tf32(acc[mi][ni][2] * sInv[rl0 + 8]));
            v1.y = __uint_as_float(f2tf32(acc[mi][ni][3] * sInv[rl0 + 8]));
            *(float2*)(C + row0 * DMODEL + col0) = v0;
            *(float2*)(C + (row0 + 8) * DMODEL + col0) = v1;
        }
    }
}

// =================================================================
// In-place LayerNorm over rows of length DMODEL (1024). 256 threads.
// =================================================================
__global__ __launch_bounds__(256) void ln_kernel(float* __restrict__ x,
                                                 const float* __restrict__ gamma,
                                                 const float* __restrict__ beta)
{
    float* row = x + (size_t)blockIdx.x * DMODEL;
    const int tid = threadIdx.x;
    __shared__ float ssum[8], ssq[8];

    float v[4];
    float s = 0.0f, sq = 0.0f;
#pragma unroll
    for (int j = 0; j < 4; j++) {
        v[j] = row[tid + j * 256];
        s += v[j];
        sq += v[j] * v[j];
    }
#pragma unroll
    for (int o = 16; o > 0; o >>= 1) {
        s  += __shfl_xor_sync(0xffffffffu, s, o);
        sq += __shfl_xor_sync(0xffffffffu, sq, o);
    }
    if ((tid & 31) == 0) { ssum[tid >> 5] = s; ssq[tid >> 5] = sq; }
    __syncthreads();
    s = 0.0f; sq = 0.0f;
#pragma unroll
    for (int j = 0; j < 8; j++) { s += ssum[j]; sq += ssq[j]; }

    const float mu = s * (1.0f / DMODEL);
    const float var = sq * (1.0f / DMODEL) - mu * mu;
    const float rstd = rsqrtf(var + 1e-6f);
#pragma unroll
    for (int j = 0; j < 4; j++) {
        const int c = tid + j * 256;
        row[c] = (v[j] - mu) * rstd * gamma[c] + beta[c];
    }
}

// =================================================================
static constexpr int GEMM_SMEM = 2 * (128 * 36 + 64 * 36) * 4;         // 55296 B
static constexpr int PROJ_SMEM = 2 * (2 * 128 * 40 + 2 * 64 * 40) * 2; // 61440 B
static constexpr int SC_SMEM   = (2 * 128 * 72 + 2 * 64 * 72) * 2;     // 55296 B
static constexpr int PV_SMEM   = PV_STAGES * (128 * 36 + 32 * 68) * 4; // 108544 B

extern "C" void kernel_launch(void* const* d_in, const int* in_sizes, int n_in,
                              void* d_out, int out_size)
{
    const float* q     = (const float*)d_in[0];
    const float* k     = (const float*)d_in[1];
    const float* v     = (const float*)d_in[2];
    const float* w_q   = (const float*)d_in[3];
    const float* w_k   = (const float*)d_in[4];
    const float* w_v   = (const float*)d_in[5];
    const float* w_fc  = (const float*)d_in[6];
    const float* gamma = (const float*)d_in[7];
    const float* beta  = (const float*)d_in[8];

    __nv_bfloat16 *qs, *ks_, *q2, *k2, *wq2, *wk2;
    float *vp, *ao, *wfr, *part;
    cudaGetSymbolAddress((void**)&qs, g_qs);
    cudaGetSymbolAddress((void**)&ks_, g_ks);
    cudaGetSymbolAddress((void**)&q2, g_q2);
    cudaGetSymbolAddress((void**)&k2, g_k2);
    cudaGetSymbolAddress((void**)&wq2, g_wq2);
    cudaGetSymbolAddress((void**)&wk2, g_wk2);
    cudaGetSymbolAddress((void**)&vp, g_vp);
    cudaGetSymbolAddress((void**)&ao, g_ao);
    cudaGetSymbolAddress((void**)&wfr, g_wf);
    cudaGetSymbolAddress((void**)&part, g_part);

    float* out  = (float*)d_out;
    float* attn = out + (size_t)MROWS * DMODEL;   // [B, H, Sq, Sk] fp32

    cudaFuncSetAttribute(proj_bf16_kernel,
                         cudaFuncAttributeMaxDynamicSharedMemorySize, PROJ_SMEM);
    cudaFuncSetAttribute(gemm_tc<true,false,true,false>,
                         cudaFuncAttributeMaxDynamicSharedMemorySize, GEMM_SMEM);
    cudaFuncSetAttribute(gemm_tc<true,true,false,true>,
                         cudaFuncAttributeMaxDynamicSharedMemorySize, GEMM_SMEM);
    cudaFuncSetAttribute(scores_kernel,
                         cudaFuncAttributeMaxDynamicSharedMemorySize, SC_SMEM);
    cudaFuncSetAttribute(pv_kernel,
                         cudaFuncAttributeMaxDynamicSharedMemorySize, PV_SMEM);

    dim3 blk(256);
    const int actBlocks = MROWS * (DMODEL / 4) / 256;   // 8192
    const int wBlocks   = DMODEL * (DMODEL / 4) / 256;  // 1024

    // --- split q, k, w_q, w_k into bf16 hi|lo planes; round w_fc ---
    split_planes<<<actBlocks, blk>>>(q, q2, MROWS);
    split_planes<<<actBlocks, blk>>>(k, k2, MROWS);
    split_planes<<<wBlocks, blk>>>(w_q, wq2, DMODEL);
    split_planes<<<wBlocks, blk>>>(w_k, wk2, DMODEL);
    round_tf32_kernel<<<wBlocks, blk>>>(w_fc, wfr, DMODEL * DMODEL / 4);

    // --- Q/K projections: zero-ALU bf16x3 GEMM from planes ---
    {
        dim3 g(DMODEL / 64, MROWS / 128, 1);
        proj_bf16_kernel<<<g, blk, PROJ_SMEM>>>(q2, wq2, qs);
        proj_bf16_kernel<<<g, blk, PROJ_SMEM>>>(k2, wk2, ks_);
    }
    // --- V projection (single tf32, output rounded to tf32) ---
    {
        dim3 g(DMODEL / 64, MROWS / 128, 1);
        gemm_tc<true,false,true,false><<<g, blk, GEMM_SMEM>>>(
            v, DMODEL, w_v, DMODEL, vp, DMODEL, DMODEL, 1.0f, nullptr);
    }

    // --- scores (bf16x3) + exp (tf32-rounded) + partials ---
    {
        dim3 g(S_LEN / 64, S_LEN / 128, NZ);
        scores_kernel<<<g, blk, SC_SMEM>>>(qs, ks_, attn, part);
    }

    // --- PV (zero-ALU tf32, 4-stage pipeline) + in-place normalization ---
    {
        dim3 g(1, S_LEN / 128, NZ);
        pv_kernel<<<g, blk, PV_SMEM>>>(attn, vp, ao, part);
    }

    // --- fc + residual (zero-ALU tf32: pre-rounded ao and w_fc) ---
    {
        dim3 g(DMODEL / 64, MROWS / 128, 1);
        gemm_tc<true,true,false,true><<<g, blk, GEMM_SMEM>>>(
            ao, DMODEL, wfr, DMODEL, out, DMODEL, DMODEL, 1.0f, q);
    }

    // --- layernorm in place ---
    ln_kernel<<<MROWS, blk>>>(out, gamma, beta);
}